// round 11
// baseline (speedup 1.0000x reference)
#include <cuda_runtime.h>
#include <cstdint>
#include <math.h>

// Problem dims
#define T_ 8
#define B_ 32
#define D_ 768
#define M_ 8
#define S_ 2
#define L_ 2
#define H_ 8
#define HD_ 96
#define d_ 384
#define P_ 16          // M_*S_
#define U_ 32          // P_*L_

typedef unsigned long long u64;

// ---------------- device state / scratch ----------------
__device__ float g_mem[M_*B_*D_];
__device__ float g_qall[(long)M_*T_*B_*D_];
__device__ float g_qk[(long)M_*H_*T_*B_*D_];   // [ (m*8+h), t*B+b, 768 ]
__device__ float g_wmem[(long)M_*H_*B_*D_];    // [ (m*8+h), b, 768 ]
__device__ float g_o[M_*B_*D_];
__device__ float g_h[P_*B_*d_];
__device__ float g_pa[U_*B_*d_];
__device__ float g_pr[U_*B_*d_];
__device__ float g_dp[U_*B_*d_];
__device__ float g_sr[U_*B_*d_];
__device__ float g_gb[U_*B_*d_];
__device__ float g_W [(long)U_*d_*d_];
__device__ float g_Wr[(long)U_*d_*d_];
__device__ float g_t1[U_*B_*d_];
__device__ float g_nt[U_*B_*3*d_];
__device__ float g_mod[U_*B_*d_];
__device__ float g_asm[2*U_*B_*d_];
__device__ float g_C[(long)2*U_*d_*d_];
__device__ float g_tmp[U_*B_*d_];
__device__ float g_outpre[M_*B_*D_];

// ---------------- f32x2 helpers ----------------
__device__ __forceinline__ u64 pack2(float x, float y) {
    u64 r;
    asm("mov.b64 %0, {%1, %2};" : "=l"(r) : "f"(x), "f"(y));
    return r;
}
__device__ __forceinline__ void fma2(u64& d, u64 a, u64 b) {
    asm("fma.rn.f32x2 %0, %1, %2, %0;" : "+l"(d) : "l"(a), "l"(b));
}
__device__ __forceinline__ float2 unpack2(u64 v) {
    float2 f;
    asm("mov.b64 {%0, %1}, %2;" : "=f"(f.x), "=f"(f.y) : "l"(v));
    return f;
}

// ---------------- generic batched tiled GEMM (f32x2) -------------------------
// SM16=false: BM=32, thread 4x4 (R4-proven). SM16=true: BM=16, thread 2x4
// (double grid for latency-bound small-M launches).
// AMODE=0: Ab = A + z*aB, row stride lda
// AMODE=1: h-layout gather (A[((z*2 + k/384)*B_ + i)*384 + k%384])
// AMODE=2: Ab = A + (z>>3)*aB + (z&7)*96, row stride lda
// wB2!=0 : Wb = W + (z>>3)*wB + (z&7)*wB2
#define AS_STRIDE 36
#define A16_ST 20
#define BS_STRIDE 68
template<int AMODE, int CMODE, bool TRANSA, bool TRANSB, bool SM16>
__global__ __launch_bounds__(128) void gemm2_k(
                        const float* __restrict__ A, long aB, int lda,
                        const float* __restrict__ W, long wB, int zwrap, long wB2,
                        const float* __restrict__ bias, long bB,
                        const float* __restrict__ add, long adB,
                        float* __restrict__ C, long cB,
                        int N, int K, float scale, int relu)
{
    __shared__ float As[16*AS_STRIDE];
    __shared__ float Bs[16*BS_STRIDE];
    const int tid = threadIdx.x;
    const int tx = tid & 15;
    const int ty = tid >> 4;
    const int z = blockIdx.z;
    const float* Ab;
    if (AMODE == 2) Ab = A + (long)(z >> 3)*aB + (long)(z & 7)*96;
    else            Ab = A + (long)z*aB;
    const float* Wb;
    if (wB2) Wb = W + (long)(z >> 3)*wB + (long)(z & 7)*wB2;
    else     Wb = W + (long)(zwrap ? (z % zwrap) : z)*wB;
    const int BM = SM16 ? 16 : 32;
    const int row0 = blockIdx.y*BM, col0 = blockIdx.x*64;
    const int NR = SM16 ? 2 : 4;

    u64 acc[4][2];
    #pragma unroll
    for (int r = 0; r < 4; r++) { acc[r][0] = 0ull; acc[r][1] = 0ull; }

    for (int k0 = 0; k0 < K; k0 += 16) {
        if (SM16) {
            if (tid < 64) {
                int r = tid >> 2, kc = (tid & 3)*4;
                float4 av;
                if (AMODE == 1) {
                    int k = k0 + kc; int sh = k / d_, kr = k % d_;
                    av = *(const float4*)&A[(((long)z*2 + sh)*B_ + row0 + r)*d_ + kr];
                } else {
                    av = *(const float4*)&Ab[(long)(row0 + r)*lda + k0 + kc];
                }
                As[(kc+0)*A16_ST + r] = av.x;
                As[(kc+1)*A16_ST + r] = av.y;
                As[(kc+2)*A16_ST + r] = av.z;
                As[(kc+3)*A16_ST + r] = av.w;
            }
        } else if (TRANSA) {
            int kk = tid >> 3, r4 = (tid & 7)*4;
            float4 av = *(const float4*)&Ab[(long)(k0 + kk)*lda + row0 + r4];
            *(float4*)&As[kk*AS_STRIDE + r4] = av;
        } else {
            int r = tid >> 2, kc = (tid & 3)*4;
            float4 av;
            if (AMODE == 1) {
                int k = k0 + kc; int sh = k / d_, kr = k % d_;
                av = *(const float4*)&A[(((long)z*2 + sh)*B_ + row0 + r)*d_ + kr];
            } else {
                av = *(const float4*)&Ab[(long)(row0 + r)*lda + k0 + kc];
            }
            As[(kc+0)*AS_STRIDE + r] = av.x;
            As[(kc+1)*AS_STRIDE + r] = av.y;
            As[(kc+2)*AS_STRIDE + r] = av.z;
            As[(kc+3)*AS_STRIDE + r] = av.w;
        }
        #pragma unroll
        for (int it = 0; it < 2; it++) {
            int e = tid + it*128;
            if (TRANSB) {
                int j = e >> 2, kc = (e & 3)*4;
                float4 wv = *(const float4*)&Wb[(long)(col0 + j)*K + k0 + kc];
                Bs[(kc+0)*BS_STRIDE + j] = wv.x;
                Bs[(kc+1)*BS_STRIDE + j] = wv.y;
                Bs[(kc+2)*BS_STRIDE + j] = wv.z;
                Bs[(kc+3)*BS_STRIDE + j] = wv.w;
            } else {
                int kk = e >> 4, j4 = (e & 15)*4;
                float4 wv = *(const float4*)&Wb[(long)(k0 + kk)*N + col0 + j4];
                *(float4*)&Bs[kk*BS_STRIDE + j4] = wv;
            }
        }
        __syncthreads();
        if (SM16) {
            #pragma unroll
            for (int kk = 0; kk < 16; kk++) {
                float2 a = *(const float2*)&As[kk*A16_ST + ty*2];
                u64 b0 = *(const u64*)&Bs[kk*BS_STRIDE + tx*4];
                u64 b1 = *(const u64*)&Bs[kk*BS_STRIDE + tx*4 + 2];
                u64 a0 = pack2(a.x, a.x);
                u64 a1 = pack2(a.y, a.y);
                fma2(acc[0][0], a0, b0); fma2(acc[0][1], a0, b1);
                fma2(acc[1][0], a1, b0); fma2(acc[1][1], a1, b1);
            }
        } else {
            #pragma unroll
            for (int kk = 0; kk < 16; kk++) {
                float4 a = *(const float4*)&As[kk*AS_STRIDE + ty*4];
                u64 b0 = *(const u64*)&Bs[kk*BS_STRIDE + tx*4];
                u64 b1 = *(const u64*)&Bs[kk*BS_STRIDE + tx*4 + 2];
                u64 a0 = pack2(a.x, a.x);
                u64 a1 = pack2(a.y, a.y);
                u64 a2 = pack2(a.z, a.z);
                u64 a3 = pack2(a.w, a.w);
                fma2(acc[0][0], a0, b0); fma2(acc[0][1], a0, b1);
                fma2(acc[1][0], a1, b0); fma2(acc[1][1], a1, b1);
                fma2(acc[2][0], a2, b0); fma2(acc[2][1], a2, b1);
                fma2(acc[3][0], a3, b0); fma2(acc[3][1], a3, b1);
            }
        }
        __syncthreads();
    }

    float* Cb = C + (long)z*cB;
    const int colb = col0 + tx*4;
    #pragma unroll
    for (int r = 0; r < 4; r++) {
        if (r >= NR) break;
        int row = row0 + ty*NR + r;
        float2 v0 = unpack2(acc[r][0]);
        float2 v1 = unpack2(acc[r][1]);
        float v[4] = {v0.x, v0.y, v1.x, v1.y};
        #pragma unroll
        for (int c = 0; c < 4; c++) {
            if (bias) v[c] += bias[(long)z*bB + colb + c];
            v[c] *= scale;
            if (add)  v[c] += add[(long)z*adB + (long)row*N + colb + c];
            if (relu) v[c] = fmaxf(v[c], 0.f);
        }
        if (CMODE) {
            int sh = colb / d_, jr = colb % d_;
            float* dst = C + (((long)z*2 + sh)*B_ + row)*d_ + jr;
            *(float4*)dst = make_float4(v[0], v[1], v[2], v[3]);
        } else {
            *(float4*)&Cb[(long)row*N + colb] = make_float4(v[0], v[1], v[2], v[3]);
        }
    }
}

// ---------------- fused scores + softmax + weighted-mem  ---------------------
__global__ __launch_bounds__(256) void wmem_k(int t)
{
    int b = blockIdx.x, m = blockIdx.y;
    int tid = threadIdx.x;
    int w = tid >> 5, lane = tid & 31;
    __shared__ float memsh[M_*D_];
    __shared__ float scr[H_*M_];

    #pragma unroll
    for (int i = 0; i < 6; i++) {
        int fe = tid + i*256;
        int s = fe / 192, j4 = (fe % 192)*4;
        *(float4*)&memsh[s*D_ + j4] = *(const float4*)&g_mem[((long)s*B_ + b)*D_ + j4];
    }
    __syncthreads();

    const float* qkrow = g_qk + (((long)(m*H_ + w))*T_*B_ + t*B_ + b)*D_;
    float qv[24];
    #pragma unroll
    for (int i = 0; i < 24; i++) qv[i] = qkrow[lane + i*32];

    for (int s = 0; s < M_; s++) {
        float p = 0.f;
        #pragma unroll
        for (int i = 0; i < 24; i++) p += qv[i]*memsh[s*D_ + lane + i*32];
        #pragma unroll
        for (int o = 16; o > 0; o >>= 1) p += __shfl_xor_sync(0xffffffffu, p, o);
        if (lane == 0) scr[w*M_ + s] = p;
    }
    __syncwarp();

    float a[M_];
    float mx = -1e30f;
    #pragma unroll
    for (int s = 0; s < M_; s++) mx = fmaxf(mx, scr[w*M_ + s]);
    float sum = 0.f;
    #pragma unroll
    for (int s = 0; s < M_; s++) { a[s] = __expf(scr[w*M_ + s] - mx); sum += a[s]; }
    float inv = 1.f / sum;
    #pragma unroll
    for (int s = 0; s < M_; s++) a[s] *= inv;

    float* dst = g_wmem + (((long)(m*H_ + w))*B_ + b)*D_;
    #pragma unroll
    for (int i = 0; i < 24; i++) {
        int j = lane + i*32;
        float acc = 0.f;
        #pragma unroll
        for (int s = 0; s < M_; s++) acc += a[s]*memsh[s*D_ + j];
        dst[j] = acc;
    }
}

// ---------------- per-head V projection ----------------
__global__ __launch_bounds__(128) void attnv_k(const float* __restrict__ w,
                                               const float* __restrict__ bias)
{
    __shared__ float As[16*36];
    __shared__ float Bs[16*36];
    const int tid = threadIdx.x;
    const int tx = tid & 7;
    const int ty = tid >> 3;
    const int z = blockIdx.z, m = z >> 3, h = z & 7;
    const int col0 = blockIdx.x*32;
    const float* Ab = g_wmem + (long)z*B_*D_;
    const float* Wb = w + (long)m*3*D_*D_ + (long)(2*D_ + h*HD_)*D_;

    u64 acc[2][2];
    acc[0][0] = acc[0][1] = acc[1][0] = acc[1][1] = 0ull;

    for (int k0 = 0; k0 < D_; k0 += 16) {
        {
            int r = tid >> 2, kc = (tid & 3)*4;
            float4 av = *(const float4*)&Ab[(long)r*D_ + k0 + kc];
            As[(kc+0)*36 + r] = av.x;
            As[(kc+1)*36 + r] = av.y;
            As[(kc+2)*36 + r] = av.z;
            As[(kc+3)*36 + r] = av.w;
        }
        {
            int j = tid >> 2, kc = (tid & 3)*4;
            float4 wv = *(const float4*)&Wb[(long)(col0 + j)*D_ + k0 + kc];
            Bs[(kc+0)*36 + j] = wv.x;
            Bs[(kc+1)*36 + j] = wv.y;
            Bs[(kc+2)*36 + j] = wv.z;
            Bs[(kc+3)*36 + j] = wv.w;
        }
        __syncthreads();
        #pragma unroll
        for (int kk = 0; kk < 16; kk++) {
            float2 a = *(const float2*)&As[kk*36 + ty*2];
            u64 b0 = *(const u64*)&Bs[kk*36 + tx*4];
            u64 b1 = *(const u64*)&Bs[kk*36 + tx*4 + 2];
            u64 a0 = pack2(a.x, a.x);
            u64 a1 = pack2(a.y, a.y);
            fma2(acc[0][0], a0, b0); fma2(acc[0][1], a0, b1);
            fma2(acc[1][0], a1, b0); fma2(acc[1][1], a1, b1);
        }
        __syncthreads();
    }

    const float* bb = bias + (long)m*3*D_ + 2*D_ + h*HD_ + col0 + tx*4;
    #pragma unroll
    for (int r = 0; r < 2; r++) {
        int row = ty*2 + r;
        float2 v0 = unpack2(acc[r][0]);
        float2 v1 = unpack2(acc[r][1]);
        float4 v = make_float4(v0.x + bb[0], v0.y + bb[1], v1.x + bb[2], v1.y + bb[3]);
        *(float4*)&g_o[((long)m*B_ + row)*D_ + h*HD_ + col0 + tx*4] = v;
    }
}

// ---------------- plastic layer kernels (batched over U_ units) --------------
__global__ void gates_k(const float* __restrict__ alpha)
{
    int idx = blockIdx.x*256 + threadIdx.x;
    if (idx >= U_*B_*d_) return;
    int j = idx % d_; int b = (idx/d_) % B_; int u = idx/(B_*d_);
    const float* nt = g_nt + ((long)(u*B_ + b))*3*d_ + j*3;
    float pd = nt[0], ps = nt[1], pg = nt[2];
    float inv = 1.f / fmaxf(ps, 1e-6f);
    float dpv = tanhf(g_dp[idx] + pd*inv);
    float srv = 1.f/(1.f + __expf(-(g_sr[idx] + ps)));
    float gbv = 1.f/(1.f + __expf(-(g_gb[idx] + pg*inv)));
    g_dp[idx] = dpv; g_sr[idx] = srv; g_gb[idx] = gbv;
    g_mod[idx] = alpha[(long)u*d_ + j] * dpv * srv;
}

__global__ void rsm_k()
{
    int row = blockIdx.x;
    int which = blockIdx.y;
    const float* src = (which ? g_pr : g_pa) + (long)row*d_;
    float* dst = g_asm + (long)which*U_*B_*d_ + (long)row*d_;
    int u = threadIdx.x;
    __shared__ float red[128];
    float v0 = src[u], v1 = src[u + 128], v2 = src[u + 256];
    float mx = fmaxf(v0, fmaxf(v1, v2));
    red[u] = mx; __syncthreads();
    #pragma unroll
    for (int o = 64; o > 0; o >>= 1) { if (u < o) red[u] = fmaxf(red[u], red[u + o]); __syncthreads(); }
    mx = red[0]; __syncthreads();
    float e0 = __expf(v0 - mx), e1 = __expf(v1 - mx), e2 = __expf(v2 - mx);
    red[u] = e0 + e1 + e2; __syncthreads();
    #pragma unroll
    for (int o = 64; o > 0; o >>= 1) { if (u < o) red[u] += red[u + o]; __syncthreads(); }
    float inv = 1.f / red[0];
    dst[u] = e0*inv; dst[u + 128] = e1*inv; dst[u + 256] = e2*inv;
}

// W_new[i][j] = W*(1-sd[i]) + rowsoftmax(W)[i][j]*C[i][j]   (sd computed in-block)
__global__ void wupd_k(const float* __restrict__ decay)
{
    int i = blockIdx.x, u = blockIdx.y, which = blockIdx.z;
    float* Wp = (which ? g_Wr : g_W) + ((long)u*d_ + i)*d_;
    const float* Cp = g_C + ((long)(which*U_ + u)*d_ + i)*d_;
    int t = threadIdx.x;
    __shared__ float red[128];
    __shared__ float sdsh;
    if (t < 32) {
        float v = g_gb[((long)u*B_ + t)*d_ + i];
        #pragma unroll
        for (int o = 16; o > 0; o >>= 1) v += __shfl_xor_sync(0xffffffffu, v, o);
        if (t == 0) {
            float s = v*(1.f/B_);
            sdsh = decay[(long)u*d_ + i] * (1.f/(1.f + __expf(-s)));
        }
    }
    float w0 = Wp[t], w1 = Wp[t + 128], w2 = Wp[t + 256];
    float mx = fmaxf(w0, fmaxf(w1, w2));
    red[t] = mx; __syncthreads();
    #pragma unroll
    for (int o = 64; o > 0; o >>= 1) { if (t < o) red[t] = fmaxf(red[t], red[t + o]); __syncthreads(); }
    mx = red[0]; __syncthreads();
    float e0 = __expf(w0 - mx), e1 = __expf(w1 - mx), e2 = __expf(w2 - mx);
    red[t] = e0 + e1 + e2; __syncthreads();
    #pragma unroll
    for (int o = 64; o > 0; o >>= 1) { if (t < o) red[t] += red[t + o]; __syncthreads(); }
    float invs = 1.f / red[0];
    float om = 1.f - sdsh;
    Wp[t]       = w0*om + e0*invs*Cp[t];
    Wp[t + 128] = w1*om + e1*invs*Cp[t + 128];
    Wp[t + 256] = w2*om + e2*invs*Cp[t + 256];
}

// ---------------- LayerNorm ----------------
__global__ void ln_k(const float* __restrict__ in,
                     float* __restrict__ out1, long o1Group,
                     float* __restrict__ out2,
                     const float* __restrict__ gam, const float* __restrict__ bet,
                     long gGroup, int N)
{
    int row = blockIdx.x;
    int u = threadIdx.x;
    int grp = row / B_, rb = row % B_;
    const float* x = in + (long)row*N;
    int nper = N / 128;
    float vals[6];
    float s = 0.f;
    for (int t = 0; t < nper; t++) { vals[t] = x[u + t*128]; s += vals[t]; }
    __shared__ float red[128];
    red[u] = s; __syncthreads();
    #pragma unroll
    for (int o = 64; o > 0; o >>= 1) { if (u < o) red[u] += red[u + o]; __syncthreads(); }
    float mu = red[0] / N; __syncthreads();
    float sq = 0.f;
    for (int t = 0; t < nper; t++) { float dv = vals[t] - mu; sq += dv*dv; }
    red[u] = sq; __syncthreads();
    #pragma unroll
    for (int o = 64; o > 0; o >>= 1) { if (u < o) red[u] += red[u + o]; __syncthreads(); }
    float rstd = rsqrtf(red[0] / N + 1e-5f);
    float* o1 = out1 + (long)grp*o1Group + (long)rb*N;
    const float* gp = gam + (long)grp*gGroup;
    const float* bp = bet + (long)grp*gGroup;
    for (int t = 0; t < nper; t++) {
        int j = u + t*128;
        float y = (vals[t] - mu)*rstd*gp[j] + bp[j];
        o1[j] = y;
        if (out2) out2[(long)row*N + j] = y;
    }
}

__global__ void clear_k()
{
    long idx = (long)blockIdx.x*256 + threadIdx.x;
    if (idx < (long)U_*B_*d_) {
        g_pa[idx] = 0.f; g_pr[idx] = 0.f; g_dp[idx] = 0.f; g_sr[idx] = 0.f; g_gb[idx] = 0.f;
    }
}

// ---------------- host launcher ----------------
extern "C" void kernel_launch(void* const* d_in, const int* in_sizes, int n_in,
                              void* d_out, int out_size)
{
    const float* x          = (const float*)d_in[0];
    const float* mem0       = (const float*)d_in[1];
    const float* attn_in_w  = (const float*)d_in[2];
    const float* attn_in_b  = (const float*)d_in[3];
    const float* attn_out_w = (const float*)d_in[4];
    const float* attn_out_b = (const float*)d_in[5];
    const float* heb_w      = (const float*)d_in[6];
    const float* heb_rw     = (const float*)d_in[7];
    const float* alpha      = (const float*)d_in[8];
    const float* decay      = (const float*)d_in[9];
    const float* ln_act_g   = (const float*)d_in[10];
    const float* ln_act_b   = (const float*)d_in[11];
    const float* ln_rec_g   = (const float*)d_in[12];
    const float* ln_rec_b   = (const float*)d_in[13];
    const float* pred_w1    = (const float*)d_in[14];
    const float* pred_b1    = (const float*)d_in[15];
    const float* pred_w2    = (const float*)d_in[16];
    const float* pred_b2    = (const float*)d_in[17];
    const float* out_w      = (const float*)d_in[18];
    const float* out_b      = (const float*)d_in[19];
    const float* ln_out_g   = (const float*)d_in[20];
    const float* ln_out_b   = (const float*)d_in[21];

    float *pmem, *pqall, *pqk, *po, *ph, *ppa, *ppr, *pt1, *pnt, *ptmp,
          *poutpre, *pW, *pWr, *pasm, *pmod, *pC;
    cudaGetSymbolAddress((void**)&pmem,    g_mem);
    cudaGetSymbolAddress((void**)&pqall,   g_qall);
    cudaGetSymbolAddress((void**)&pqk,     g_qk);
    cudaGetSymbolAddress((void**)&po,      g_o);
    cudaGetSymbolAddress((void**)&ph,      g_h);
    cudaGetSymbolAddress((void**)&ppa,     g_pa);
    cudaGetSymbolAddress((void**)&ppr,     g_pr);
    cudaGetSymbolAddress((void**)&pt1,     g_t1);
    cudaGetSymbolAddress((void**)&pnt,     g_nt);
    cudaGetSymbolAddress((void**)&ptmp,    g_tmp);
    cudaGetSymbolAddress((void**)&poutpre, g_outpre);
    cudaGetSymbolAddress((void**)&pW,      g_W);
    cudaGetSymbolAddress((void**)&pWr,     g_Wr);
    cudaGetSymbolAddress((void**)&pasm,    g_asm);
    cudaGetSymbolAddress((void**)&pmod,    g_mod);
    cudaGetSymbolAddress((void**)&pC,      g_C);

    static cudaStream_t s1 = nullptr;
    static cudaEvent_t evFork = nullptr, evHeb = nullptr;
    if (!s1) {
        cudaStreamCreateWithFlags(&s1, cudaStreamNonBlocking);
        cudaEventCreateWithFlags(&evFork, cudaEventDisableTiming);
        cudaEventCreateWithFlags(&evHeb,  cudaEventDisableTiming);
    }
    cudaStream_t s0 = 0;

    const float qscale = 1.f / sqrtf((float)HD_);

    // init state (s0)
    cudaMemcpyAsync(pW,  heb_w,  sizeof(float)*(long)U_*d_*d_, cudaMemcpyDeviceToDevice, s0);
    cudaMemcpyAsync(pWr, heb_rw, sizeof(float)*(long)U_*d_*d_, cudaMemcpyDeviceToDevice, s0);
    cudaMemcpyAsync(pmem, mem0,  sizeof(float)*M_*B_*D_,       cudaMemcpyDeviceToDevice, s0);
    clear_k<<<(U_*B_*d_ + 255)/256, 256, 0, s0>>>();

    // q for all timesteps, then qk = qh @ Wk (per head)
    gemm2_k<0,0,false,true,false><<<dim3(12, 8, M_), 128, 0, s0>>>(x, 0, D_,
        attn_in_w, (long)3*D_*D_, 0, 0, attn_in_b, (long)3*D_, nullptr, 0,
        pqall, (long)T_*B_*D_, D_, D_, qscale, 0);
    gemm2_k<2,0,false,false,false><<<dim3(12, 8, M_*H_), 128, 0, s0>>>(pqall, (long)T_*B_*D_, D_,
        attn_in_w + (long)D_*D_, (long)3*D_*D_, 0, (long)HD_*D_,
        nullptr, 0, nullptr, 0,
        pqk, (long)T_*B_*D_, D_, HD_, 1.f, 0);

    for (int t = 0; t < T_; t++) {
        cudaEventRecord(evFork, s0);
        cudaStreamWaitEvent(s1, evFork, 0);

        // ---- Hebbian chain on s1 (SM16 tiles for small-M GEMMs) ----
        gemm2_k<0,0,false,false,true><<<dim3(6, 2, U_), 128, 0, s1>>>(ppa, (long)B_*d_, d_,
            pred_w1, (long)d_*d_, 0, 0, pred_b1, (long)d_, nullptr, 0,
            pt1, (long)B_*d_, d_, d_, 1.f, 1);
        gemm2_k<0,0,false,false,true><<<dim3(18, 2, U_), 128, 0, s1>>>(pt1, (long)B_*d_, d_,
            pred_w2, (long)d_*3*d_, 0, 0, pred_b2, (long)3*d_, nullptr, 0,
            pnt, (long)B_*3*d_, 3*d_, d_, 1.f, 0);
        gates_k<<<(U_*B_*d_ + 255)/256, 256, 0, s1>>>(alpha);
        rsm_k<<<dim3(U_*B_, 2), 128, 0, s1>>>();
        gemm2_k<0,0,true,false,false><<<dim3(6, 12, 2*U_), 128, 0, s1>>>(pasm, (long)B_*d_, d_,
            pmod, (long)B_*d_, U_, 0, nullptr, 0, nullptr, 0,
            pC, (long)d_*d_, d_, B_, 1.f/B_, 0);
        wupd_k<<<dim3(d_, U_, 2), 128, 0, s1>>>(decay);
        gemm2_k<0,0,false,false,true><<<dim3(6, 2, U_), 128, 0, s1>>>(ppa, (long)B_*d_, d_,
            pWr, (long)d_*d_, 0, 0, nullptr, 0, nullptr, 0,
            ptmp, (long)B_*d_, d_, d_, 1.f, 0);
        ln_k<<<U_*B_, 128, 0, s1>>>(ptmp, ppr, (long)B_*d_, nullptr,
            ln_rec_g, ln_rec_b, (long)d_, d_);
        cudaEventRecord(evHeb, s1);

        // ---- attention chain on s0 ----
        wmem_k<<<dim3(B_, M_), 256, 0, s0>>>(t);
        attnv_k<<<dim3(3, 1, M_*H_), 128, 0, s0>>>(attn_in_w, attn_in_b);
        gemm2_k<0,1,false,true,true><<<dim3(12, 2, M_), 128, 0, s0>>>(po, (long)B_*D_, D_,
            attn_out_w, (long)D_*D_, 0, 0, attn_out_b, (long)D_, nullptr, 0,
            ph, 0, D_, D_, 1.f, 0);

        cudaStreamWaitEvent(s0, evHeb, 0);

        for (int l = 0; l < L_; l++) {
            gemm2_k<0,0,false,false,true><<<dim3(6, 2, P_), 128, 0, s0>>>(ph, (long)B_*d_, d_,
                pW + (long)l*d_*d_, (long)L_*d_*d_, 0, 0, nullptr, 0,
                ppr + (long)l*B_*d_, (long)L_*B_*d_,
                ptmp, (long)B_*d_, d_, d_, 1.f, 1);
            ln_k<<<P_*B_, 128, 0, s0>>>(ptmp, ppa + (long)l*B_*d_, (long)L_*B_*d_, ph,
                ln_act_g + (long)l*d_, ln_act_b + (long)l*d_, (long)L_*d_, d_);
        }

        gemm2_k<1,0,false,true,true><<<dim3(12, 2, M_), 128, 0, s0>>>(ph, 0, 0,
            out_w, (long)D_*D_, 0, 0, out_b, (long)D_, nullptr, 0,
            poutpre, (long)B_*D_, D_, D_, 1.f, 0);
        ln_k<<<M_*B_, 128, 0, s0>>>(poutpre, pmem, (long)B_*D_, nullptr,
            ln_out_g, ln_out_b, (long)D_, D_);
    }

    cudaMemcpyAsync(d_out, pmem, sizeof(float)*M_*B_*D_, cudaMemcpyDeviceToDevice, s0);
}

// round 12
// speedup vs baseline: 1.2089x; 1.2089x over previous
#include <cuda_runtime.h>
#include <cstdint>
#include <math.h>

// Problem dims
#define T_ 8
#define B_ 32
#define D_ 768
#define M_ 8
#define S_ 2
#define L_ 2
#define H_ 8
#define HD_ 96
#define d_ 384
#define P_ 16          // M_*S_
#define U_ 32          // P_*L_

typedef unsigned long long u64;

// ---------------- device state / scratch ----------------
__device__ float g_mem[M_*B_*D_];
__device__ float g_qall[(long)M_*T_*B_*D_];
__device__ float g_qk[(long)M_*H_*T_*B_*D_];   // [ (m*8+h), t*B+b, 768 ]
__device__ float g_wmem[(long)M_*H_*B_*D_];    // [ (m*8+h), b, 768 ]
__device__ float g_o[M_*B_*D_];
__device__ float g_h[P_*B_*d_];
__device__ float g_pa[U_*B_*d_];
__device__ float g_pr[U_*B_*d_];
__device__ float g_dp[U_*B_*d_];
__device__ float g_sr[U_*B_*d_];
__device__ float g_gb[U_*B_*d_];
__device__ float g_W [(long)U_*d_*d_];
__device__ float g_Wr[(long)U_*d_*d_];
__device__ float g_t1[U_*B_*d_];
__device__ float g_nt[U_*B_*3*d_];
__device__ float g_mod[U_*B_*d_];
__device__ float g_asm[2*U_*B_*d_];
__device__ float g_C[(long)2*U_*d_*d_];
__device__ float g_tmp[U_*B_*d_];
__device__ float g_outpre[M_*B_*D_];

// ---------------- f32x2 helpers ----------------
__device__ __forceinline__ u64 pack2(float x, float y) {
    u64 r;
    asm("mov.b64 %0, {%1, %2};" : "=l"(r) : "f"(x), "f"(y));
    return r;
}
__device__ __forceinline__ void fma2(u64& d, u64 a, u64 b) {
    asm("fma.rn.f32x2 %0, %1, %2, %0;" : "+l"(d) : "l"(a), "l"(b));
}
__device__ __forceinline__ void add2(u64& d, u64 o) {
    asm("add.rn.f32x2 %0, %0, %1;" : "+l"(d) : "l"(o));
}
__device__ __forceinline__ float2 unpack2(u64 v) {
    float2 f;
    asm("mov.b64 {%0, %1}, %2;" : "=f"(f.x), "=f"(f.y) : "l"(v));
    return f;
}

#define AS_STRIDE 36
#define BS_STRIDE 68

// ---------------- gemm2_k: R4-proven BM32 4x4 tile, 128 threads --------------
// AMODE=0: Ab = A + z*aB, stride lda. AMODE=2: Ab = A + (z>>3)*aB + (z&7)*96.
// wB2!=0 : Wb = W + (z>>3)*wB + (z&7)*wB2.
template<int AMODE, bool TRANSA, bool TRANSB>
__global__ __launch_bounds__(128) void gemm2_k(
                        const float* __restrict__ A, long aB, int lda,
                        const float* __restrict__ W, long wB, int zwrap, long wB2,
                        const float* __restrict__ bias, long bB,
                        float* __restrict__ C, long cB,
                        int N, int K, float scale)
{
    __shared__ float As[16*AS_STRIDE];
    __shared__ float Bs[16*BS_STRIDE];
    const int tid = threadIdx.x;
    const int tx = tid & 15;
    const int ty = tid >> 4;
    const int z = blockIdx.z;
    const float* Ab;
    if (AMODE == 2) Ab = A + (long)(z >> 3)*aB + (long)(z & 7)*96;
    else            Ab = A + (long)z*aB;
    const float* Wb;
    if (wB2) Wb = W + (long)(z >> 3)*wB + (long)(z & 7)*wB2;
    else     Wb = W + (long)(zwrap ? (z % zwrap) : z)*wB;
    const int row0 = blockIdx.y*32, col0 = blockIdx.x*64;

    u64 acc[4][2];
    #pragma unroll
    for (int r = 0; r < 4; r++) { acc[r][0] = 0ull; acc[r][1] = 0ull; }

    for (int k0 = 0; k0 < K; k0 += 16) {
        if (TRANSA) {
            int kk = tid >> 3, r4 = (tid & 7)*4;
            float4 av = *(const float4*)&Ab[(long)(k0 + kk)*lda + row0 + r4];
            *(float4*)&As[kk*AS_STRIDE + r4] = av;
        } else {
            int r = tid >> 2, kc = (tid & 3)*4;
            float4 av = *(const float4*)&Ab[(long)(row0 + r)*lda + k0 + kc];
            As[(kc+0)*AS_STRIDE + r] = av.x;
            As[(kc+1)*AS_STRIDE + r] = av.y;
            As[(kc+2)*AS_STRIDE + r] = av.z;
            As[(kc+3)*AS_STRIDE + r] = av.w;
        }
        #pragma unroll
        for (int it = 0; it < 2; it++) {
            int e = tid + it*128;
            if (TRANSB) {
                int j = e >> 2, kc = (e & 3)*4;
                float4 wv = *(const float4*)&Wb[(long)(col0 + j)*K + k0 + kc];
                Bs[(kc+0)*BS_STRIDE + j] = wv.x;
                Bs[(kc+1)*BS_STRIDE + j] = wv.y;
                Bs[(kc+2)*BS_STRIDE + j] = wv.z;
                Bs[(kc+3)*BS_STRIDE + j] = wv.w;
            } else {
                int kk = e >> 4, j4 = (e & 15)*4;
                float4 wv = *(const float4*)&Wb[(long)(k0 + kk)*N + col0 + j4];
                *(float4*)&Bs[kk*BS_STRIDE + j4] = wv;
            }
        }
        __syncthreads();
        #pragma unroll
        for (int kk = 0; kk < 16; kk++) {
            float4 a = *(const float4*)&As[kk*AS_STRIDE + ty*4];
            u64 b0 = *(const u64*)&Bs[kk*BS_STRIDE + tx*4];
            u64 b1 = *(const u64*)&Bs[kk*BS_STRIDE + tx*4 + 2];
            u64 a0 = pack2(a.x, a.x);
            u64 a1 = pack2(a.y, a.y);
            u64 a2 = pack2(a.z, a.z);
            u64 a3 = pack2(a.w, a.w);
            fma2(acc[0][0], a0, b0); fma2(acc[0][1], a0, b1);
            fma2(acc[1][0], a1, b0); fma2(acc[1][1], a1, b1);
            fma2(acc[2][0], a2, b0); fma2(acc[2][1], a2, b1);
            fma2(acc[3][0], a3, b0); fma2(acc[3][1], a3, b1);
        }
        __syncthreads();
    }

    float* Cb = C + (long)z*cB;
    const int colb = col0 + tx*4;
    #pragma unroll
    for (int r = 0; r < 4; r++) {
        int row = row0 + ty*4 + r;
        float2 v0 = unpack2(acc[r][0]);
        float2 v1 = unpack2(acc[r][1]);
        float v[4] = {v0.x, v0.y, v1.x, v1.y};
        #pragma unroll
        for (int c = 0; c < 4; c++) {
            if (bias) v[c] += bias[(long)z*bB + colb + c];
            v[c] *= scale;
        }
        *(float4*)&Cb[(long)row*N + colb] = make_float4(v[0], v[1], v[2], v[3]);
    }
}

// ---------------- gemm3_k: intra-block split-K (256 thr, 2 k-groups) ---------
// Same 4x4 inner loop per group; group g covers k-tiles g*16, g*16+32, ...
// AMODE=1: A from h-layout gather. CMODE=1: C scatter to h-layout.
template<int AMODE, int CMODE, bool TRANSB>
__global__ __launch_bounds__(256) void gemm3_k(
                        const float* __restrict__ A, long aB, int lda,
                        const float* __restrict__ W, long wB,
                        const float* __restrict__ bias, long bB,
                        const float* __restrict__ add, long adB,
                        float* __restrict__ C, long cB,
                        int N, int K, float scale, int relu)
{
    __shared__ float As[2][16*AS_STRIDE];
    __shared__ float Bs[2][16*BS_STRIDE];
    __shared__ u64 red[128*8];
    const int tid = threadIdx.x;
    const int kg = tid >> 7;
    const int t = tid & 127;
    const int tx = t & 15;
    const int ty = t >> 4;
    const int z = blockIdx.z;
    const float* Ab = A + (long)z*aB;
    const float* Wb = W + (long)z*wB;
    const int row0 = blockIdx.y*32, col0 = blockIdx.x*64;

    u64 acc[4][2];
    #pragma unroll
    for (int r = 0; r < 4; r++) { acc[r][0] = 0ull; acc[r][1] = 0ull; }

    for (int k0 = kg*16; k0 < K; k0 += 32) {
        {
            int r = t >> 2, kc = (t & 3)*4;
            float4 av;
            if (AMODE == 1) {
                int k = k0 + kc; int sh = k / d_, kr = k % d_;
                av = *(const float4*)&A[(((long)z*2 + sh)*B_ + row0 + r)*d_ + kr];
            } else {
                av = *(const float4*)&Ab[(long)(row0 + r)*lda + k0 + kc];
            }
            As[kg][(kc+0)*AS_STRIDE + r] = av.x;
            As[kg][(kc+1)*AS_STRIDE + r] = av.y;
            As[kg][(kc+2)*AS_STRIDE + r] = av.z;
            As[kg][(kc+3)*AS_STRIDE + r] = av.w;
        }
        #pragma unroll
        for (int it = 0; it < 2; it++) {
            int e = t + it*128;
            if (TRANSB) {
                int j = e >> 2, kc = (e & 3)*4;
                float4 wv = *(const float4*)&Wb[(long)(col0 + j)*K + k0 + kc];
                Bs[kg][(kc+0)*BS_STRIDE + j] = wv.x;
                Bs[kg][(kc+1)*BS_STRIDE + j] = wv.y;
                Bs[kg][(kc+2)*BS_STRIDE + j] = wv.z;
                Bs[kg][(kc+3)*BS_STRIDE + j] = wv.w;
            } else {
                int kk = e >> 4, j4 = (e & 15)*4;
                float4 wv = *(const float4*)&Wb[(long)(k0 + kk)*N + col0 + j4];
                *(float4*)&Bs[kg][kk*BS_STRIDE + j4] = wv;
            }
        }
        __syncthreads();
        #pragma unroll
        for (int kk = 0; kk < 16; kk++) {
            float4 a = *(const float4*)&As[kg][kk*AS_STRIDE + ty*4];
            u64 b0 = *(const u64*)&Bs[kg][kk*BS_STRIDE + tx*4];
            u64 b1 = *(const u64*)&Bs[kg][kk*BS_STRIDE + tx*4 + 2];
            u64 a0 = pack2(a.x, a.x);
            u64 a1 = pack2(a.y, a.y);
            u64 a2 = pack2(a.z, a.z);
            u64 a3 = pack2(a.w, a.w);
            fma2(acc[0][0], a0, b0); fma2(acc[0][1], a0, b1);
            fma2(acc[1][0], a1, b0); fma2(acc[1][1], a1, b1);
            fma2(acc[2][0], a2, b0); fma2(acc[2][1], a2, b1);
            fma2(acc[3][0], a3, b0); fma2(acc[3][1], a3, b1);
        }
        __syncthreads();
    }

    // combine k-groups: kg1 spills, kg0 adds + epilogue
    if (kg == 1) {
        #pragma unroll
        for (int r = 0; r < 4; r++) {
            red[(r*2 + 0)*128 + t] = acc[r][0];
            red[(r*2 + 1)*128 + t] = acc[r][1];
        }
    }
    __syncthreads();
    if (kg == 0) {
        #pragma unroll
        for (int r = 0; r < 4; r++) {
            add2(acc[r][0], red[(r*2 + 0)*128 + t]);
            add2(acc[r][1], red[(r*2 + 1)*128 + t]);
        }
        float* Cb = C + (long)z*cB;
        const int colb = col0 + tx*4;
        #pragma unroll
        for (int r = 0; r < 4; r++) {
            int row = row0 + ty*4 + r;
            float2 v0 = unpack2(acc[r][0]);
            float2 v1 = unpack2(acc[r][1]);
            float v[4] = {v0.x, v0.y, v1.x, v1.y};
            #pragma unroll
            for (int c = 0; c < 4; c++) {
                if (bias) v[c] += bias[(long)z*bB + colb + c];
                v[c] *= scale;
                if (add)  v[c] += add[(long)z*adB + (long)row*N + colb + c];
                if (relu) v[c] = fmaxf(v[c], 0.f);
            }
            if (CMODE) {
                int sh = colb / d_, jr = colb % d_;
                float* dst = C + (((long)z*2 + sh)*B_ + row)*d_ + jr;
                *(float4*)dst = make_float4(v[0], v[1], v[2], v[3]);
            } else {
                *(float4*)&Cb[(long)row*N + colb] = make_float4(v[0], v[1], v[2], v[3]);
            }
        }
    }
}

// ---------------- fused scores + softmax + weighted-mem  ---------------------
__global__ __launch_bounds__(256) void wmem_k(int t)
{
    int b = blockIdx.x, m = blockIdx.y;
    int tid = threadIdx.x;
    int w = tid >> 5, lane = tid & 31;
    __shared__ float memsh[M_*D_];
    __shared__ float scr[H_*M_];

    #pragma unroll
    for (int i = 0; i < 6; i++) {
        int fe = tid + i*256;
        int s = fe / 192, j4 = (fe % 192)*4;
        *(float4*)&memsh[s*D_ + j4] = *(const float4*)&g_mem[((long)s*B_ + b)*D_ + j4];
    }
    __syncthreads();

    const float* qkrow = g_qk + (((long)(m*H_ + w))*T_*B_ + t*B_ + b)*D_;
    float qv[24];
    #pragma unroll
    for (int i = 0; i < 24; i++) qv[i] = qkrow[lane + i*32];

    for (int s = 0; s < M_; s++) {
        float p = 0.f;
        #pragma unroll
        for (int i = 0; i < 24; i++) p += qv[i]*memsh[s*D_ + lane + i*32];
        #pragma unroll
        for (int o = 16; o > 0; o >>= 1) p += __shfl_xor_sync(0xffffffffu, p, o);
        if (lane == 0) scr[w*M_ + s] = p;
    }
    __syncwarp();

    float a[M_];
    float mx = -1e30f;
    #pragma unroll
    for (int s = 0; s < M_; s++) mx = fmaxf(mx, scr[w*M_ + s]);
    float sum = 0.f;
    #pragma unroll
    for (int s = 0; s < M_; s++) { a[s] = __expf(scr[w*M_ + s] - mx); sum += a[s]; }
    float inv = 1.f / sum;
    #pragma unroll
    for (int s = 0; s < M_; s++) a[s] *= inv;

    float* dst = g_wmem + (((long)(m*H_ + w))*B_ + b)*D_;
    #pragma unroll
    for (int i = 0; i < 24; i++) {
        int j = lane + i*32;
        float acc = 0.f;
        #pragma unroll
        for (int s = 0; s < M_; s++) acc += a[s]*memsh[s*D_ + j];
        dst[j] = acc;
    }
}

// ---------------- per-head V projection ----------------
__global__ __launch_bounds__(128) void attnv_k(const float* __restrict__ w,
                                               const float* __restrict__ bias)
{
    __shared__ float As[16*36];
    __shared__ float Bs[16*36];
    const int tid = threadIdx.x;
    const int tx = tid & 7;
    const int ty = tid >> 3;
    const int z = blockIdx.z, m = z >> 3, h = z & 7;
    const int col0 = blockIdx.x*32;
    const float* Ab = g_wmem + (long)z*B_*D_;
    const float* Wb = w + (long)m*3*D_*D_ + (long)(2*D_ + h*HD_)*D_;

    u64 acc[2][2];
    acc[0][0] = acc[0][1] = acc[1][0] = acc[1][1] = 0ull;

    for (int k0 = 0; k0 < D_; k0 += 16) {
        {
            int r = tid >> 2, kc = (tid & 3)*4;
            float4 av = *(const float4*)&Ab[(long)r*D_ + k0 + kc];
            As[(kc+0)*36 + r] = av.x;
            As[(kc+1)*36 + r] = av.y;
            As[(kc+2)*36 + r] = av.z;
            As[(kc+3)*36 + r] = av.w;
        }
        {
            int j = tid >> 2, kc = (tid & 3)*4;
            float4 wv = *(const float4*)&Wb[(long)(col0 + j)*D_ + k0 + kc];
            Bs[(kc+0)*36 + j] = wv.x;
            Bs[(kc+1)*36 + j] = wv.y;
            Bs[(kc+2)*36 + j] = wv.z;
            Bs[(kc+3)*36 + j] = wv.w;
        }
        __syncthreads();
        #pragma unroll
        for (int kk = 0; kk < 16; kk++) {
            float2 a = *(const float2*)&As[kk*36 + ty*2];
            u64 b0 = *(const u64*)&Bs[kk*36 + tx*4];
            u64 b1 = *(const u64*)&Bs[kk*36 + tx*4 + 2];
            u64 a0 = pack2(a.x, a.x);
            u64 a1 = pack2(a.y, a.y);
            fma2(acc[0][0], a0, b0); fma2(acc[0][1], a0, b1);
            fma2(acc[1][0], a1, b0); fma2(acc[1][1], a1, b1);
        }
        __syncthreads();
    }

    const float* bb = bias + (long)m*3*D_ + 2*D_ + h*HD_ + col0 + tx*4;
    #pragma unroll
    for (int r = 0; r < 2; r++) {
        int row = ty*2 + r;
        float2 v0 = unpack2(acc[r][0]);
        float2 v1 = unpack2(acc[r][1]);
        float4 v = make_float4(v0.x + bb[0], v0.y + bb[1], v1.x + bb[2], v1.y + bb[3]);
        *(float4*)&g_o[((long)m*B_ + row)*D_ + h*HD_ + col0 + tx*4] = v;
    }
}

// ---------------- plastic layer kernels (batched over U_ units) --------------
__global__ void gates_k(const float* __restrict__ alpha)
{
    int idx = blockIdx.x*256 + threadIdx.x;
    if (idx >= U_*B_*d_) return;
    int j = idx % d_; int b = (idx/d_) % B_; int u = idx/(B_*d_);
    const float* nt = g_nt + ((long)(u*B_ + b))*3*d_ + j*3;
    float pd = nt[0], ps = nt[1], pg = nt[2];
    float inv = 1.f / fmaxf(ps, 1e-6f);
    float dpv = tanhf(g_dp[idx] + pd*inv);
    float srv = 1.f/(1.f + __expf(-(g_sr[idx] + ps)));
    float gbv = 1.f/(1.f + __expf(-(g_gb[idx] + pg*inv)));
    g_dp[idx] = dpv; g_sr[idx] = srv; g_gb[idx] = gbv;
    g_mod[idx] = alpha[(long)u*d_ + j] * dpv * srv;
}

__global__ void rsm_k()
{
    int row = blockIdx.x;
    int which = blockIdx.y;
    const float* src = (which ? g_pr : g_pa) + (long)row*d_;
    float* dst = g_asm + (long)which*U_*B_*d_ + (long)row*d_;
    int u = threadIdx.x;
    __shared__ float red[128];
    float v0 = src[u], v1 = src[u + 128], v2 = src[u + 256];
    float mx = fmaxf(v0, fmaxf(v1, v2));
    red[u] = mx; __syncthreads();
    #pragma unroll
    for (int o = 64; o > 0; o >>= 1) { if (u < o) red[u] = fmaxf(red[u], red[u + o]); __syncthreads(); }
    mx = red[0]; __syncthreads();
    float e0 = __expf(v0 - mx), e1 = __expf(v1 - mx), e2 = __expf(v2 - mx);
    red[u] = e0 + e1 + e2; __syncthreads();
    #pragma unroll
    for (int o = 64; o > 0; o >>= 1) { if (u < o) red[u] += red[u + o]; __syncthreads(); }
    float inv = 1.f / red[0];
    dst[u] = e0*inv; dst[u + 128] = e1*inv; dst[u + 256] = e2*inv;
}

// W_new[i][j] = W*(1-sd[i]) + rowsoftmax(W)[i][j]*C[i][j]   (sd computed in-block)
__global__ void wupd_k(const float* __restrict__ decay)
{
    int i = blockIdx.x, u = blockIdx.y, which = blockIdx.z;
    float* Wp = (which ? g_Wr : g_W) + ((long)u*d_ + i)*d_;
    const float* Cp = g_C + ((long)(which*U_ + u)*d_ + i)*d_;
    int t = threadIdx.x;
    __shared__ float red[128];
    __shared__ float sdsh;
    if (t < 32) {
        float v = g_gb[((long)u*B_ + t)*d_ + i];
        #pragma unroll
        for (int o = 16; o > 0; o >>= 1) v += __shfl_xor_sync(0xffffffffu, v, o);
        if (t == 0) {
            float s = v*(1.f/B_);
            sdsh = decay[(long)u*d_ + i] * (1.f/(1.f + __expf(-s)));
        }
    }
    float w0 = Wp[t], w1 = Wp[t + 128], w2 = Wp[t + 256];
    float mx = fmaxf(w0, fmaxf(w1, w2));
    red[t] = mx; __syncthreads();
    #pragma unroll
    for (int o = 64; o > 0; o >>= 1) { if (t < o) red[t] = fmaxf(red[t], red[t + o]); __syncthreads(); }
    mx = red[0]; __syncthreads();
    float e0 = __expf(w0 - mx), e1 = __expf(w1 - mx), e2 = __expf(w2 - mx);
    red[t] = e0 + e1 + e2; __syncthreads();
    #pragma unroll
    for (int o = 64; o > 0; o >>= 1) { if (t < o) red[t] += red[t + o]; __syncthreads(); }
    float invs = 1.f / red[0];
    float om = 1.f - sdsh;
    Wp[t]       = w0*om + e0*invs*Cp[t];
    Wp[t + 128] = w1*om + e1*invs*Cp[t + 128];
    Wp[t + 256] = w2*om + e2*invs*Cp[t + 256];
}

// ---------------- LayerNorm ----------------
__global__ void ln_k(const float* __restrict__ in,
                     float* __restrict__ out1, long o1Group,
                     float* __restrict__ out2,
                     const float* __restrict__ gam, const float* __restrict__ bet,
                     long gGroup, int N)
{
    int row = blockIdx.x;
    int u = threadIdx.x;
    int grp = row / B_, rb = row % B_;
    const float* x = in + (long)row*N;
    int nper = N / 128;
    float vals[6];
    float s = 0.f;
    for (int t = 0; t < nper; t++) { vals[t] = x[u + t*128]; s += vals[t]; }
    __shared__ float red[128];
    red[u] = s; __syncthreads();
    #pragma unroll
    for (int o = 64; o > 0; o >>= 1) { if (u < o) red[u] += red[u + o]; __syncthreads(); }
    float mu = red[0] / N; __syncthreads();
    float sq = 0.f;
    for (int t = 0; t < nper; t++) { float dv = vals[t] - mu; sq += dv*dv; }
    red[u] = sq; __syncthreads();
    #pragma unroll
    for (int o = 64; o > 0; o >>= 1) { if (u < o) red[u] += red[u + o]; __syncthreads(); }
    float rstd = rsqrtf(red[0] / N + 1e-5f);
    float* o1 = out1 + (long)grp*o1Group + (long)rb*N;
    const float* gp = gam + (long)grp*gGroup;
    const float* bp = bet + (long)grp*gGroup;
    for (int t = 0; t < nper; t++) {
        int j = u + t*128;
        float y = (vals[t] - mu)*rstd*gp[j] + bp[j];
        o1[j] = y;
        if (out2) out2[(long)row*N + j] = y;
    }
}

__global__ void clear_k()
{
    long idx = (long)blockIdx.x*256 + threadIdx.x;
    if (idx < (long)U_*B_*d_) {
        g_pa[idx] = 0.f; g_pr[idx] = 0.f; g_dp[idx] = 0.f; g_sr[idx] = 0.f; g_gb[idx] = 0.f;
    }
}

// ---------------- host launcher ----------------
extern "C" void kernel_launch(void* const* d_in, const int* in_sizes, int n_in,
                              void* d_out, int out_size)
{
    const float* x          = (const float*)d_in[0];
    const float* mem0       = (const float*)d_in[1];
    const float* attn_in_w  = (const float*)d_in[2];
    const float* attn_in_b  = (const float*)d_in[3];
    const float* attn_out_w = (const float*)d_in[4];
    const float* attn_out_b = (const float*)d_in[5];
    const float* heb_w      = (const float*)d_in[6];
    const float* heb_rw     = (const float*)d_in[7];
    const float* alpha      = (const float*)d_in[8];
    const float* decay      = (const float*)d_in[9];
    const float* ln_act_g   = (const float*)d_in[10];
    const float* ln_act_b   = (const float*)d_in[11];
    const float* ln_rec_g   = (const float*)d_in[12];
    const float* ln_rec_b   = (const float*)d_in[13];
    const float* pred_w1    = (const float*)d_in[14];
    const float* pred_b1    = (const float*)d_in[15];
    const float* pred_w2    = (const float*)d_in[16];
    const float* pred_b2    = (const float*)d_in[17];
    const float* out_w      = (const float*)d_in[18];
    const float* out_b      = (const float*)d_in[19];
    const float* ln_out_g   = (const float*)d_in[20];
    const float* ln_out_b   = (const float*)d_in[21];

    float *pmem, *pqall, *pqk, *po, *ph, *ppa, *ppr, *pt1, *pnt, *ptmp,
          *poutpre, *pW, *pWr, *pasm, *pmod, *pC;
    cudaGetSymbolAddress((void**)&pmem,    g_mem);
    cudaGetSymbolAddress((void**)&pqall,   g_qall);
    cudaGetSymbolAddress((void**)&pqk,     g_qk);
    cudaGetSymbolAddress((void**)&po,      g_o);
    cudaGetSymbolAddress((void**)&ph,      g_h);
    cudaGetSymbolAddress((void**)&ppa,     g_pa);
    cudaGetSymbolAddress((void**)&ppr,     g_pr);
    cudaGetSymbolAddress((void**)&pt1,     g_t1);
    cudaGetSymbolAddress((void**)&pnt,     g_nt);
    cudaGetSymbolAddress((void**)&ptmp,    g_tmp);
    cudaGetSymbolAddress((void**)&poutpre, g_outpre);
    cudaGetSymbolAddress((void**)&pW,      g_W);
    cudaGetSymbolAddress((void**)&pWr,     g_Wr);
    cudaGetSymbolAddress((void**)&pasm,    g_asm);
    cudaGetSymbolAddress((void**)&pmod,    g_mod);
    cudaGetSymbolAddress((void**)&pC,      g_C);

    static cudaStream_t s1 = nullptr;
    static cudaEvent_t evFork = nullptr, evHeb = nullptr;
    if (!s1) {
        cudaStreamCreateWithFlags(&s1, cudaStreamNonBlocking);
        cudaEventCreateWithFlags(&evFork, cudaEventDisableTiming);
        cudaEventCreateWithFlags(&evHeb,  cudaEventDisableTiming);
    }
    cudaStream_t s0 = 0;

    const float qscale = 1.f / sqrtf((float)HD_);

    // init state (s0)
    cudaMemcpyAsync(pW,  heb_w,  sizeof(float)*(long)U_*d_*d_, cudaMemcpyDeviceToDevice, s0);
    cudaMemcpyAsync(pWr, heb_rw, sizeof(float)*(long)U_*d_*d_, cudaMemcpyDeviceToDevice, s0);
    cudaMemcpyAsync(pmem, mem0,  sizeof(float)*M_*B_*D_,       cudaMemcpyDeviceToDevice, s0);
    clear_k<<<(U_*B_*d_ + 255)/256, 256, 0, s0>>>();

    // q for all timesteps, then qk = qh @ Wk (per head)
    gemm2_k<0,false,true><<<dim3(12, 8, M_), 128, 0, s0>>>(x, 0, D_,
        attn_in_w, (long)3*D_*D_, 0, 0, attn_in_b, (long)3*D_,
        pqall, (long)T_*B_*D_, D_, D_, qscale);
    gemm2_k<2,false,false><<<dim3(12, 8, M_*H_), 128, 0, s0>>>(pqall, (long)T_*B_*D_, D_,
        attn_in_w + (long)D_*D_, (long)3*D_*D_, 0, (long)HD_*D_,
        nullptr, 0,
        pqk, (long)T_*B_*D_, D_, HD_, 1.f);

    for (int t = 0; t < T_; t++) {
        cudaEventRecord(evFork, s0);
        cudaStreamWaitEvent(s1, evFork, 0);

        // ---- Hebbian chain on s1 (split-K GEMMs; rsm hoisted to front) ----
        rsm_k<<<dim3(U_*B_, 2), 128, 0, s1>>>();
        gemm3_k<0,0,false><<<dim3(6, 1, U_), 256, 0, s1>>>(ppa, (long)B_*d_, d_,
            pred_w1, (long)d_*d_, pred_b1, (long)d_, nullptr, 0,
            pt1, (long)B_*d_, d_, d_, 1.f, 1);
        gemm3_k<0,0,false><<<dim3(18, 1, U_), 256, 0, s1>>>(pt1, (long)B_*d_, d_,
            pred_w2, (long)d_*3*d_, pred_b2, (long)3*d_, nullptr, 0,
            pnt, (long)B_*3*d_, 3*d_, d_, 1.f, 0);
        gates_k<<<(U_*B_*d_ + 255)/256, 256, 0, s1>>>(alpha);
        gemm2_k<0,true,false><<<dim3(6, 12, 2*U_), 128, 0, s1>>>(pasm, (long)B_*d_, d_,
            pmod, (long)B_*d_, U_, 0, nullptr, 0,
            pC, (long)d_*d_, d_, B_, 1.f/B_);
        wupd_k<<<dim3(d_, U_, 2), 128, 0, s1>>>(decay);
        gemm3_k<0,0,false><<<dim3(6, 1, U_), 256, 0, s1>>>(ppa, (long)B_*d_, d_,
            pWr, (long)d_*d_, nullptr, 0, nullptr, 0,
            ptmp, (long)B_*d_, d_, d_, 1.f, 0);
        ln_k<<<U_*B_, 128, 0, s1>>>(ptmp, ppr, (long)B_*d_, nullptr,
            ln_rec_g, ln_rec_b, (long)d_, d_);
        cudaEventRecord(evHeb, s1);

        // ---- attention chain on s0 ----
        wmem_k<<<dim3(B_, M_), 256, 0, s0>>>(t);
        attnv_k<<<dim3(3, 1, M_*H_), 128, 0, s0>>>(attn_in_w, attn_in_b);
        gemm3_k<0,1,true><<<dim3(12, 1, M_), 256, 0, s0>>>(po, (long)B_*D_, D_,
            attn_out_w, (long)D_*D_, attn_out_b, (long)D_, nullptr, 0,
            ph, 0, D_, D_, 1.f, 0);

        cudaStreamWaitEvent(s0, evHeb, 0);

        for (int l = 0; l < L_; l++) {
            gemm3_k<0,0,false><<<dim3(6, 1, P_), 256, 0, s0>>>(ph, (long)B_*d_, d_,
                pW + (long)l*d_*d_, (long)L_*d_*d_, nullptr, 0,
                ppr + (long)l*B_*d_, (long)L_*B_*d_,
                ptmp, (long)B_*d_, d_, d_, 1.f, 1);
            ln_k<<<P_*B_, 128, 0, s0>>>(ptmp, ppa + (long)l*B_*d_, (long)L_*B_*d_, ph,
                ln_act_g + (long)l*d_, ln_act_b + (long)l*d_, (long)L_*d_, d_);
        }

        gemm3_k<1,0,true><<<dim3(12, 1, M_), 256, 0, s0>>>(ph, 0, 0,
            out_w, (long)D_*D_, out_b, (long)D_, nullptr, 0,
            poutpre, (long)B_*D_, D_, D_, 1.f, 0);
        ln_k<<<M_*B_, 128, 0, s0>>>(poutpre, pmem, (long)B_*D_, nullptr,
            ln_out_g, ln_out_b, (long)D_, D_);
    }

    cudaMemcpyAsync(d_out, pmem, sizeof(float)*M_*B_*D_, cudaMemcpyDeviceToDevice, s0);
}

// round 13
// speedup vs baseline: 1.3193x; 1.0913x over previous
#include <cuda_runtime.h>
#include <cstdint>
#include <math.h>

// Problem dims
#define T_ 8
#define B_ 32
#define D_ 768
#define M_ 8
#define S_ 2
#define L_ 2
#define H_ 8
#define HD_ 96
#define d_ 384
#define P_ 16          // M_*S_
#define U_ 32          // P_*L_

typedef unsigned long long u64;

// ---------------- device state / scratch ----------------
__device__ float g_mem[M_*B_*D_];
__device__ float g_qall[(long)M_*T_*B_*D_];
__device__ float g_qk[(long)M_*H_*T_*B_*D_];
__device__ float g_wmem[(long)M_*H_*B_*D_];
__device__ float g_o[M_*B_*D_];
__device__ float g_h[P_*B_*d_];
__device__ float g_pa[U_*B_*d_];
__device__ float g_pr[U_*B_*d_];
__device__ float g_dp[U_*B_*d_];
__device__ float g_sr[U_*B_*d_];
__device__ float g_gb[U_*B_*d_];
__device__ float g_W [(long)U_*d_*d_];
__device__ float g_Wr[(long)U_*d_*d_];
__device__ float g_t1[U_*B_*d_];
__device__ float g_nt[U_*B_*3*d_];
__device__ float g_mod[U_*B_*d_];
__device__ float g_asm[2*U_*B_*d_];
__device__ float g_C[(long)2*U_*d_*d_];
__device__ float g_tmp[U_*B_*d_];
__device__ float g_outpre[M_*B_*D_];

// ---------------- f32x2 helpers ----------------
__device__ __forceinline__ u64 pack2(float x, float y) {
    u64 r;
    asm("mov.b64 %0, {%1, %2};" : "=l"(r) : "f"(x), "f"(y));
    return r;
}
__device__ __forceinline__ void fma2(u64& d, u64 a, u64 b) {
    asm("fma.rn.f32x2 %0, %1, %2, %0;" : "+l"(d) : "l"(a), "l"(b));
}
__device__ __forceinline__ void add2(u64& d, u64 o) {
    asm("add.rn.f32x2 %0, %0, %1;" : "+l"(d) : "l"(o));
}
__device__ __forceinline__ float2 unpack2(u64 v) {
    float2 f;
    asm("mov.b64 {%0, %1}, %2;" : "=f"(f.x), "=f"(f.y) : "l"(v));
    return f;
}

#define AS_STRIDE 36
#define BS_STRIDE 68

// ---------------- gemm2_k: R4-proven BM32 4x4 tile, 128 threads --------------
// AMODE=0: Ab = A + z*aB, stride lda. AMODE=2: Ab = A + (z>>3)*aB + (z&7)*96.
// wB2!=0 : Wb = W + (z>>3)*wB + (z&7)*wB2.
template<int AMODE, bool TRANSA, bool TRANSB>
__global__ __launch_bounds__(128) void gemm2_k(
                        const float* __restrict__ A, long aB, int lda,
                        const float* __restrict__ W, long wB, int zwrap, long wB2,
                        const float* __restrict__ bias, long bB,
                        float* __restrict__ C, long cB,
                        int N, int K, float scale)
{
    __shared__ float As[16*AS_STRIDE];
    __shared__ float Bs[16*BS_STRIDE];
    const int tid = threadIdx.x;
    const int tx = tid & 15;
    const int ty = tid >> 4;
    const int z = blockIdx.z;
    const float* Ab;
    if (AMODE == 2) Ab = A + (long)(z >> 3)*aB + (long)(z & 7)*96;
    else            Ab = A + (long)z*aB;
    const float* Wb;
    if (wB2) Wb = W + (long)(z >> 3)*wB + (long)(z & 7)*wB2;
    else     Wb = W + (long)(zwrap ? (z % zwrap) : z)*wB;
    const int row0 = blockIdx.y*32, col0 = blockIdx.x*64;

    u64 acc[4][2];
    #pragma unroll
    for (int r = 0; r < 4; r++) { acc[r][0] = 0ull; acc[r][1] = 0ull; }

    for (int k0 = 0; k0 < K; k0 += 16) {
        if (TRANSA) {
            int kk = tid >> 3, r4 = (tid & 7)*4;
            float4 av = *(const float4*)&Ab[(long)(k0 + kk)*lda + row0 + r4];
            *(float4*)&As[kk*AS_STRIDE + r4] = av;
        } else {
            int r = tid >> 2, kc = (tid & 3)*4;
            float4 av = *(const float4*)&Ab[(long)(row0 + r)*lda + k0 + kc];
            As[(kc+0)*AS_STRIDE + r] = av.x;
            As[(kc+1)*AS_STRIDE + r] = av.y;
            As[(kc+2)*AS_STRIDE + r] = av.z;
            As[(kc+3)*AS_STRIDE + r] = av.w;
        }
        #pragma unroll
        for (int it = 0; it < 2; it++) {
            int e = tid + it*128;
            if (TRANSB) {
                int j = e >> 2, kc = (e & 3)*4;
                float4 wv = *(const float4*)&Wb[(long)(col0 + j)*K + k0 + kc];
                Bs[(kc+0)*BS_STRIDE + j] = wv.x;
                Bs[(kc+1)*BS_STRIDE + j] = wv.y;
                Bs[(kc+2)*BS_STRIDE + j] = wv.z;
                Bs[(kc+3)*BS_STRIDE + j] = wv.w;
            } else {
                int kk = e >> 4, j4 = (e & 15)*4;
                float4 wv = *(const float4*)&Wb[(long)(k0 + kk)*N + col0 + j4];
                *(float4*)&Bs[kk*BS_STRIDE + j4] = wv;
            }
        }
        __syncthreads();
        #pragma unroll
        for (int kk = 0; kk < 16; kk++) {
            float4 a = *(const float4*)&As[kk*AS_STRIDE + ty*4];
            u64 b0 = *(const u64*)&Bs[kk*BS_STRIDE + tx*4];
            u64 b1 = *(const u64*)&Bs[kk*BS_STRIDE + tx*4 + 2];
            u64 a0 = pack2(a.x, a.x);
            u64 a1 = pack2(a.y, a.y);
            u64 a2 = pack2(a.z, a.z);
            u64 a3 = pack2(a.w, a.w);
            fma2(acc[0][0], a0, b0); fma2(acc[0][1], a0, b1);
            fma2(acc[1][0], a1, b0); fma2(acc[1][1], a1, b1);
            fma2(acc[2][0], a2, b0); fma2(acc[2][1], a2, b1);
            fma2(acc[3][0], a3, b0); fma2(acc[3][1], a3, b1);
        }
        __syncthreads();
    }

    float* Cb = C + (long)z*cB;
    const int colb = col0 + tx*4;
    #pragma unroll
    for (int r = 0; r < 4; r++) {
        int row = row0 + ty*4 + r;
        float2 v0 = unpack2(acc[r][0]);
        float2 v1 = unpack2(acc[r][1]);
        float v[4] = {v0.x, v0.y, v1.x, v1.y};
        #pragma unroll
        for (int c = 0; c < 4; c++) {
            if (bias) v[c] += bias[(long)z*bB + colb + c];
            v[c] *= scale;
        }
        *(float4*)&Cb[(long)row*N + colb] = make_float4(v[0], v[1], v[2], v[3]);
    }
}

// ---------------- gemm3_k: intra-block split-K, 4 k-groups, 512 threads ------
// Group g covers k-tiles g*16, g*16+64, ... Two-round smem tree combine.
// AMODE=1: A from h-layout gather. CMODE=1: C scatter to h-layout.
template<int AMODE, int CMODE, bool TRANSB>
__global__ __launch_bounds__(512) void gemm3_k(
                        const float* __restrict__ A, long aB, int lda,
                        const float* __restrict__ W, long wB,
                        const float* __restrict__ bias, long bB,
                        const float* __restrict__ add, long adB,
                        float* __restrict__ C, long cB,
                        int N, int K, float scale, int relu)
{
    __shared__ float As[4][16*AS_STRIDE];
    __shared__ float Bs[4][16*BS_STRIDE];
    __shared__ u64 red[2][128*8];
    const int tid = threadIdx.x;
    const int kg = tid >> 7;       // 0..3
    const int t = tid & 127;
    const int tx = t & 15;
    const int ty = t >> 4;
    const int z = blockIdx.z;
    const float* Ab = A + (long)z*aB;
    const float* Wb = W + (long)z*wB;
    const int row0 = blockIdx.y*32, col0 = blockIdx.x*64;

    u64 acc[4][2];
    #pragma unroll
    for (int r = 0; r < 4; r++) { acc[r][0] = 0ull; acc[r][1] = 0ull; }

    for (int k0 = kg*16; k0 < K; k0 += 64) {
        {
            int r = t >> 2, kc = (t & 3)*4;
            float4 av;
            if (AMODE == 1) {
                int k = k0 + kc; int sh = k / d_, kr = k % d_;
                av = *(const float4*)&A[(((long)z*2 + sh)*B_ + row0 + r)*d_ + kr];
            } else {
                av = *(const float4*)&Ab[(long)(row0 + r)*lda + k0 + kc];
            }
            As[kg][(kc+0)*AS_STRIDE + r] = av.x;
            As[kg][(kc+1)*AS_STRIDE + r] = av.y;
            As[kg][(kc+2)*AS_STRIDE + r] = av.z;
            As[kg][(kc+3)*AS_STRIDE + r] = av.w;
        }
        #pragma unroll
        for (int it = 0; it < 2; it++) {
            int e = t + it*128;
            if (TRANSB) {
                int j = e >> 2, kc = (e & 3)*4;
                float4 wv = *(const float4*)&Wb[(long)(col0 + j)*K + k0 + kc];
                Bs[kg][(kc+0)*BS_STRIDE + j] = wv.x;
                Bs[kg][(kc+1)*BS_STRIDE + j] = wv.y;
                Bs[kg][(kc+2)*BS_STRIDE + j] = wv.z;
                Bs[kg][(kc+3)*BS_STRIDE + j] = wv.w;
            } else {
                int kk = e >> 4, j4 = (e & 15)*4;
                float4 wv = *(const float4*)&Wb[(long)(k0 + kk)*N + col0 + j4];
                *(float4*)&Bs[kg][kk*BS_STRIDE + j4] = wv;
            }
        }
        __syncthreads();
        #pragma unroll
        for (int kk = 0; kk < 16; kk++) {
            float4 a = *(const float4*)&As[kg][kk*AS_STRIDE + ty*4];
            u64 b0 = *(const u64*)&Bs[kg][kk*BS_STRIDE + tx*4];
            u64 b1 = *(const u64*)&Bs[kg][kk*BS_STRIDE + tx*4 + 2];
            u64 a0 = pack2(a.x, a.x);
            u64 a1 = pack2(a.y, a.y);
            u64 a2 = pack2(a.z, a.z);
            u64 a3 = pack2(a.w, a.w);
            fma2(acc[0][0], a0, b0); fma2(acc[0][1], a0, b1);
            fma2(acc[1][0], a1, b0); fma2(acc[1][1], a1, b1);
            fma2(acc[2][0], a2, b0); fma2(acc[2][1], a2, b1);
            fma2(acc[3][0], a3, b0); fma2(acc[3][1], a3, b1);
        }
        __syncthreads();
    }

    // round 1: odd groups spill, even groups add
    if (kg & 1) {
        #pragma unroll
        for (int r = 0; r < 4; r++) {
            red[kg >> 1][(r*2 + 0)*128 + t] = acc[r][0];
            red[kg >> 1][(r*2 + 1)*128 + t] = acc[r][1];
        }
    }
    __syncthreads();
    if (!(kg & 1)) {
        #pragma unroll
        for (int r = 0; r < 4; r++) {
            add2(acc[r][0], red[kg >> 1][(r*2 + 0)*128 + t]);
            add2(acc[r][1], red[kg >> 1][(r*2 + 1)*128 + t]);
        }
    }
    __syncthreads();
    // round 2: group 2 spills, group 0 adds + epilogue
    if (kg == 2) {
        #pragma unroll
        for (int r = 0; r < 4; r++) {
            red[0][(r*2 + 0)*128 + t] = acc[r][0];
            red[0][(r*2 + 1)*128 + t] = acc[r][1];
        }
    }
    __syncthreads();
    if (kg == 0) {
        #pragma unroll
        for (int r = 0; r < 4; r++) {
            add2(acc[r][0], red[0][(r*2 + 0)*128 + t]);
            add2(acc[r][1], red[0][(r*2 + 1)*128 + t]);
        }
        float* Cb = C + (long)z*cB;
        const int colb = col0 + tx*4;
        #pragma unroll
        for (int r = 0; r < 4; r++) {
            int row = row0 + ty*4 + r;
            float2 v0 = unpack2(acc[r][0]);
            float2 v1 = unpack2(acc[r][1]);
            float v[4] = {v0.x, v0.y, v1.x, v1.y};
            #pragma unroll
            for (int c = 0; c < 4; c++) {
                if (bias) v[c] += bias[(long)z*bB + colb + c];
                v[c] *= scale;
                if (add)  v[c] += add[(long)z*adB + (long)row*N + colb + c];
                if (relu) v[c] = fmaxf(v[c], 0.f);
            }
            if (CMODE) {
                int sh = colb / d_, jr = colb % d_;
                float* dst = C + (((long)z*2 + sh)*B_ + row)*d_ + jr;
                *(float4*)dst = make_float4(v[0], v[1], v[2], v[3]);
            } else {
                *(float4*)&Cb[(long)row*N + colb] = make_float4(v[0], v[1], v[2], v[3]);
            }
        }
    }
}

// ---------------- fused scores + softmax + weighted-mem  ---------------------
__global__ __launch_bounds__(256) void wmem_k(int t)
{
    int b = blockIdx.x, m = blockIdx.y;
    int tid = threadIdx.x;
    int w = tid >> 5, lane = tid & 31;
    __shared__ float memsh[M_*D_];
    __shared__ float scr[H_*M_];

    #pragma unroll
    for (int i = 0; i < 6; i++) {
        int fe = tid + i*256;
        int s = fe / 192, j4 = (fe % 192)*4;
        *(float4*)&memsh[s*D_ + j4] = *(const float4*)&g_mem[((long)s*B_ + b)*D_ + j4];
    }
    __syncthreads();

    const float* qkrow = g_qk + (((long)(m*H_ + w))*T_*B_ + t*B_ + b)*D_;
    float qv[24];
    #pragma unroll
    for (int i = 0; i < 24; i++) qv[i] = qkrow[lane + i*32];

    for (int s = 0; s < M_; s++) {
        float p = 0.f;
        #pragma unroll
        for (int i = 0; i < 24; i++) p += qv[i]*memsh[s*D_ + lane + i*32];
        #pragma unroll
        for (int o = 16; o > 0; o >>= 1) p += __shfl_xor_sync(0xffffffffu, p, o);
        if (lane == 0) scr[w*M_ + s] = p;
    }
    __syncwarp();

    float a[M_];
    float mx = -1e30f;
    #pragma unroll
    for (int s = 0; s < M_; s++) mx = fmaxf(mx, scr[w*M_ + s]);
    float sum = 0.f;
    #pragma unroll
    for (int s = 0; s < M_; s++) { a[s] = __expf(scr[w*M_ + s] - mx); sum += a[s]; }
    float inv = 1.f / sum;
    #pragma unroll
    for (int s = 0; s < M_; s++) a[s] *= inv;

    float* dst = g_wmem + (((long)(m*H_ + w))*B_ + b)*D_;
    #pragma unroll
    for (int i = 0; i < 24; i++) {
        int j = lane + i*32;
        float acc = 0.f;
        #pragma unroll
        for (int s = 0; s < M_; s++) acc += a[s]*memsh[s*D_ + j];
        dst[j] = acc;
    }
}

// ---------------- per-head V projection ----------------
__global__ __launch_bounds__(128) void attnv_k(const float* __restrict__ w,
                                               const float* __restrict__ bias)
{
    __shared__ float As[16*36];
    __shared__ float Bs[16*36];
    const int tid = threadIdx.x;
    const int tx = tid & 7;
    const int ty = tid >> 3;
    const int z = blockIdx.z, m = z >> 3, h = z & 7;
    const int col0 = blockIdx.x*32;
    const float* Ab = g_wmem + (long)z*B_*D_;
    const float* Wb = w + (long)m*3*D_*D_ + (long)(2*D_ + h*HD_)*D_;

    u64 acc[2][2];
    acc[0][0] = acc[0][1] = acc[1][0] = acc[1][1] = 0ull;

    for (int k0 = 0; k0 < D_; k0 += 16) {
        {
            int r = tid >> 2, kc = (tid & 3)*4;
            float4 av = *(const float4*)&Ab[(long)r*D_ + k0 + kc];
            As[(kc+0)*36 + r] = av.x;
            As[(kc+1)*36 + r] = av.y;
            As[(kc+2)*36 + r] = av.z;
            As[(kc+3)*36 + r] = av.w;
        }
        {
            int j = tid >> 2, kc = (tid & 3)*4;
            float4 wv = *(const float4*)&Wb[(long)(col0 + j)*D_ + k0 + kc];
            Bs[(kc+0)*36 + j] = wv.x;
            Bs[(kc+1)*36 + j] = wv.y;
            Bs[(kc+2)*36 + j] = wv.z;
            Bs[(kc+3)*36 + j] = wv.w;
        }
        __syncthreads();
        #pragma unroll
        for (int kk = 0; kk < 16; kk++) {
            float2 a = *(const float2*)&As[kk*36 + ty*2];
            u64 b0 = *(const u64*)&Bs[kk*36 + tx*4];
            u64 b1 = *(const u64*)&Bs[kk*36 + tx*4 + 2];
            u64 a0 = pack2(a.x, a.x);
            u64 a1 = pack2(a.y, a.y);
            fma2(acc[0][0], a0, b0); fma2(acc[0][1], a0, b1);
            fma2(acc[1][0], a1, b0); fma2(acc[1][1], a1, b1);
        }
        __syncthreads();
    }

    const float* bb = bias + (long)m*3*D_ + 2*D_ + h*HD_ + col0 + tx*4;
    #pragma unroll
    for (int r = 0; r < 2; r++) {
        int row = ty*2 + r;
        float2 v0 = unpack2(acc[r][0]);
        float2 v1 = unpack2(acc[r][1]);
        float4 v = make_float4(v0.x + bb[0], v0.y + bb[1], v1.x + bb[2], v1.y + bb[3]);
        *(float4*)&g_o[((long)m*B_ + row)*D_ + h*HD_ + col0 + tx*4] = v;
    }
}

// ---------------- plastic layer kernels (batched over U_ units) --------------
__global__ void gates_k(const float* __restrict__ alpha)
{
    int idx = blockIdx.x*256 + threadIdx.x;
    if (idx >= U_*B_*d_) return;
    int j = idx % d_; int b = (idx/d_) % B_; int u = idx/(B_*d_);
    const float* nt = g_nt + ((long)(u*B_ + b))*3*d_ + j*3;
    float pd = nt[0], ps = nt[1], pg = nt[2];
    float inv = 1.f / fmaxf(ps, 1e-6f);
    float dpv = tanhf(g_dp[idx] + pd*inv);
    float srv = 1.f/(1.f + __expf(-(g_sr[idx] + ps)));
    float gbv = 1.f/(1.f + __expf(-(g_gb[idx] + pg*inv)));
    g_dp[idx] = dpv; g_sr[idx] = srv; g_gb[idx] = gbv;
    g_mod[idx] = alpha[(long)u*d_ + j] * dpv * srv;
}

__global__ void rsm_k()
{
    int row = blockIdx.x;
    int which = blockIdx.y;
    const float* src = (which ? g_pr : g_pa) + (long)row*d_;
    float* dst = g_asm + (long)which*U_*B_*d_ + (long)row*d_;
    int u = threadIdx.x;
    __shared__ float red[128];
    float v0 = src[u], v1 = src[u + 128], v2 = src[u + 256];
    float mx = fmaxf(v0, fmaxf(v1, v2));
    red[u] = mx; __syncthreads();
    #pragma unroll
    for (int o = 64; o > 0; o >>= 1) { if (u < o) red[u] = fmaxf(red[u], red[u + o]); __syncthreads(); }
    mx = red[0]; __syncthreads();
    float e0 = __expf(v0 - mx), e1 = __expf(v1 - mx), e2 = __expf(v2 - mx);
    red[u] = e0 + e1 + e2; __syncthreads();
    #pragma unroll
    for (int o = 64; o > 0; o >>= 1) { if (u < o) red[u] += red[u + o]; __syncthreads(); }
    float inv = 1.f / red[0];
    dst[u] = e0*inv; dst[u + 128] = e1*inv; dst[u + 256] = e2*inv;
}

// W_new[i][j] = W*(1-sd[i]) + rowsoftmax(W)[i][j]*C[i][j]   (sd in-block)
__global__ void wupd_k(const float* __restrict__ decay, int which)
{
    int i = blockIdx.x, u = blockIdx.y;
    float* Wp = (which ? g_Wr : g_W) + ((long)u*d_ + i)*d_;
    const float* Cp = g_C + ((long)(which*U_ + u)*d_ + i)*d_;
    int t = threadIdx.x;
    __shared__ float red[128];
    __shared__ float sdsh;
    if (t < 32) {
        float v = g_gb[((long)u*B_ + t)*d_ + i];
        #pragma unroll
        for (int o = 16; o > 0; o >>= 1) v += __shfl_xor_sync(0xffffffffu, v, o);
        if (t == 0) {
            float s = v*(1.f/B_);
            sdsh = decay[(long)u*d_ + i] * (1.f/(1.f + __expf(-s)));
        }
    }
    float w0 = Wp[t], w1 = Wp[t + 128], w2 = Wp[t + 256];
    float mx = fmaxf(w0, fmaxf(w1, w2));
    red[t] = mx; __syncthreads();
    #pragma unroll
    for (int o = 64; o > 0; o >>= 1) { if (t < o) red[t] = fmaxf(red[t], red[t + o]); __syncthreads(); }
    mx = red[0]; __syncthreads();
    float e0 = __expf(w0 - mx), e1 = __expf(w1 - mx), e2 = __expf(w2 - mx);
    red[t] = e0 + e1 + e2; __syncthreads();
    #pragma unroll
    for (int o = 64; o > 0; o >>= 1) { if (t < o) red[t] += red[t + o]; __syncthreads(); }
    float invs = 1.f / red[0];
    float om = 1.f - sdsh;
    Wp[t]       = w0*om + e0*invs*Cp[t];
    Wp[t + 128] = w1*om + e1*invs*Cp[t + 128];
    Wp[t + 256] = w2*om + e2*invs*Cp[t + 256];
}

// ---------------- LayerNorm ----------------
__global__ void ln_k(const float* __restrict__ in,
                     float* __restrict__ out1, long o1Group,
                     float* __restrict__ out2,
                     const float* __restrict__ gam, const float* __restrict__ bet,
                     long gGroup, int N)
{
    int row = blockIdx.x;
    int u = threadIdx.x;
    int grp = row / B_, rb = row % B_;
    const float* x = in + (long)row*N;
    int nper = N / 128;
    float vals[6];
    float s = 0.f;
    for (int t = 0; t < nper; t++) { vals[t] = x[u + t*128]; s += vals[t]; }
    __shared__ float red[128];
    red[u] = s; __syncthreads();
    #pragma unroll
    for (int o = 64; o > 0; o >>= 1) { if (u < o) red[u] += red[u + o]; __syncthreads(); }
    float mu = red[0] / N; __syncthreads();
    float sq = 0.f;
    for (int t = 0; t < nper; t++) { float dv = vals[t] - mu; sq += dv*dv; }
    red[u] = sq; __syncthreads();
    #pragma unroll
    for (int o = 64; o > 0; o >>= 1) { if (u < o) red[u] += red[u + o]; __syncthreads(); }
    float rstd = rsqrtf(red[0] / N + 1e-5f);
    float* o1 = out1 + (long)grp*o1Group + (long)rb*N;
    const float* gp = gam + (long)grp*gGroup;
    const float* bp = bet + (long)grp*gGroup;
    for (int t = 0; t < nper; t++) {
        int j = u + t*128;
        float y = (vals[t] - mu)*rstd*gp[j] + bp[j];
        o1[j] = y;
        if (out2) out2[(long)row*N + j] = y;
    }
}

__global__ void clear_k()
{
    long idx = (long)blockIdx.x*256 + threadIdx.x;
    if (idx < (long)U_*B_*d_) {
        g_pa[idx] = 0.f; g_pr[idx] = 0.f; g_dp[idx] = 0.f; g_sr[idx] = 0.f; g_gb[idx] = 0.f;
    }
}

// ---------------- host launcher ----------------
extern "C" void kernel_launch(void* const* d_in, const int* in_sizes, int n_in,
                              void* d_out, int out_size)
{
    const float* x          = (const float*)d_in[0];
    const float* mem0       = (const float*)d_in[1];
    const float* attn_in_w  = (const float*)d_in[2];
    const float* attn_in_b  = (const float*)d_in[3];
    const float* attn_out_w = (const float*)d_in[4];
    const float* attn_out_b = (const float*)d_in[5];
    const float* heb_w      = (const float*)d_in[6];
    const float* heb_rw     = (const float*)d_in[7];
    const float* alpha      = (const float*)d_in[8];
    const float* decay      = (const float*)d_in[9];
    const float* ln_act_g   = (const float*)d_in[10];
    const float* ln_act_b   = (const float*)d_in[11];
    const float* ln_rec_g   = (const float*)d_in[12];
    const float* ln_rec_b   = (const float*)d_in[13];
    const float* pred_w1    = (const float*)d_in[14];
    const float* pred_b1    = (const float*)d_in[15];
    const float* pred_w2    = (const float*)d_in[16];
    const float* pred_b2    = (const float*)d_in[17];
    const float* out_w      = (const float*)d_in[18];
    const float* out_b      = (const float*)d_in[19];
    const float* ln_out_g   = (const float*)d_in[20];
    const float* ln_out_b   = (const float*)d_in[21];

    float *pmem, *pqall, *pqk, *po, *ph, *ppa, *ppr, *pt1, *pnt, *ptmp,
          *poutpre, *pW, *pWr, *pasm, *pmod, *pC;
    cudaGetSymbolAddress((void**)&pmem,    g_mem);
    cudaGetSymbolAddress((void**)&pqall,   g_qall);
    cudaGetSymbolAddress((void**)&pqk,     g_qk);
    cudaGetSymbolAddress((void**)&po,      g_o);
    cudaGetSymbolAddress((void**)&ph,      g_h);
    cudaGetSymbolAddress((void**)&ppa,     g_pa);
    cudaGetSymbolAddress((void**)&ppr,     g_pr);
    cudaGetSymbolAddress((void**)&pt1,     g_t1);
    cudaGetSymbolAddress((void**)&pnt,     g_nt);
    cudaGetSymbolAddress((void**)&ptmp,    g_tmp);
    cudaGetSymbolAddress((void**)&poutpre, g_outpre);
    cudaGetSymbolAddress((void**)&pW,      g_W);
    cudaGetSymbolAddress((void**)&pWr,     g_Wr);
    cudaGetSymbolAddress((void**)&pasm,    g_asm);
    cudaGetSymbolAddress((void**)&pmod,    g_mod);
    cudaGetSymbolAddress((void**)&pC,      g_C);

    static cudaStream_t s1 = nullptr, s2 = nullptr;
    static cudaEvent_t evFork = nullptr, evHeb = nullptr, evGates = nullptr, evW = nullptr;
    if (!s1) {
        cudaStreamCreateWithFlags(&s1, cudaStreamNonBlocking);
        cudaStreamCreateWithFlags(&s2, cudaStreamNonBlocking);
        cudaEventCreateWithFlags(&evFork,  cudaEventDisableTiming);
        cudaEventCreateWithFlags(&evHeb,   cudaEventDisableTiming);
        cudaEventCreateWithFlags(&evGates, cudaEventDisableTiming);
        cudaEventCreateWithFlags(&evW,     cudaEventDisableTiming);
    }
    cudaStream_t s0 = 0;

    const float qscale = 1.f / sqrtf((float)HD_);

    // init state (s0)
    cudaMemcpyAsync(pW,  heb_w,  sizeof(float)*(long)U_*d_*d_, cudaMemcpyDeviceToDevice, s0);
    cudaMemcpyAsync(pWr, heb_rw, sizeof(float)*(long)U_*d_*d_, cudaMemcpyDeviceToDevice, s0);
    cudaMemcpyAsync(pmem, mem0,  sizeof(float)*M_*B_*D_,       cudaMemcpyDeviceToDevice, s0);
    clear_k<<<(U_*B_*d_ + 255)/256, 256, 0, s0>>>();

    // q for all timesteps, then qk = qh @ Wk (per head)
    gemm2_k<0,false,true><<<dim3(12, 8, M_), 128, 0, s0>>>(x, 0, D_,
        attn_in_w, (long)3*D_*D_, 0, 0, attn_in_b, (long)3*D_,
        pqall, (long)T_*B_*D_, D_, D_, qscale);
    gemm2_k<2,false,false><<<dim3(12, 8, M_*H_), 128, 0, s0>>>(pqall, (long)T_*B_*D_, D_,
        attn_in_w + (long)D_*D_, (long)3*D_*D_, 0, (long)HD_*D_,
        nullptr, 0,
        pqk, (long)T_*B_*D_, D_, HD_, 1.f);

    for (int t = 0; t < T_; t++) {
        cudaEventRecord(evFork, s0);
        cudaStreamWaitEvent(s1, evFork, 0);

        // ---- Hebbian chain on s1; W-half update forked to s2 ----
        rsm_k<<<dim3(U_*B_, 2), 128, 0, s1>>>();
        gemm3_k<0,0,false><<<dim3(6, 1, U_), 512, 0, s1>>>(ppa, (long)B_*d_, d_,
            pred_w1, (long)d_*d_, pred_b1, (long)d_, nullptr, 0,
            pt1, (long)B_*d_, d_, d_, 1.f, 1);
        gemm3_k<0,0,false><<<dim3(18, 1, U_), 512, 0, s1>>>(pt1, (long)B_*d_, d_,
            pred_w2, (long)d_*3*d_, pred_b2, (long)3*d_, nullptr, 0,
            pnt, (long)B_*3*d_, 3*d_, d_, 1.f, 0);
        gates_k<<<(U_*B_*d_ + 255)/256, 256, 0, s1>>>(alpha);
        cudaEventRecord(evGates, s1);

        // s2: W-half (outer which=0 + wupd W) — joins at acts
        cudaStreamWaitEvent(s2, evGates, 0);
        gemm2_k<0,true,false><<<dim3(6, 12, U_), 128, 0, s2>>>(pasm, (long)B_*d_, d_,
            pmod, (long)B_*d_, 0, 0, nullptr, 0,
            pC, (long)d_*d_, d_, B_, 1.f/B_);
        wupd_k<<<dim3(d_, U_), 128, 0, s2>>>(decay, 0);
        cudaEventRecord(evW, s2);

        // s1: Wr-half (critical path to rec/pr)
        gemm2_k<0,true,false><<<dim3(6, 12, U_), 128, 0, s1>>>(pasm + (long)U_*B_*d_, (long)B_*d_, d_,
            pmod, (long)B_*d_, 0, 0, nullptr, 0,
            pC + (long)U_*d_*d_, (long)d_*d_, d_, B_, 1.f/B_);
        wupd_k<<<dim3(d_, U_), 128, 0, s1>>>(decay, 1);
        gemm3_k<0,0,false><<<dim3(6, 1, U_), 512, 0, s1>>>(ppa, (long)B_*d_, d_,
            pWr, (long)d_*d_, nullptr, 0, nullptr, 0,
            ptmp, (long)B_*d_, d_, d_, 1.f, 0);
        ln_k<<<U_*B_, 128, 0, s1>>>(ptmp, ppr, (long)B_*d_, nullptr,
            ln_rec_g, ln_rec_b, (long)d_, d_);
        cudaEventRecord(evHeb, s1);

        // ---- attention chain on s0 ----
        wmem_k<<<dim3(B_, M_), 256, 0, s0>>>(t);
        attnv_k<<<dim3(3, 1, M_*H_), 128, 0, s0>>>(attn_in_w, attn_in_b);
        gemm3_k<0,1,true><<<dim3(12, 1, M_), 512, 0, s0>>>(po, (long)B_*D_, D_,
            attn_out_w, (long)D_*D_, attn_out_b, (long)D_, nullptr, 0,
            ph, 0, D_, D_, 1.f, 0);

        cudaStreamWaitEvent(s0, evHeb, 0);
        cudaStreamWaitEvent(s0, evW, 0);

        for (int l = 0; l < L_; l++) {
            gemm3_k<0,0,false><<<dim3(6, 1, P_), 512, 0, s0>>>(ph, (long)B_*d_, d_,
                pW + (long)l*d_*d_, (long)L_*d_*d_, nullptr, 0,
                ppr + (long)l*B_*d_, (long)L_*B_*d_,
                ptmp, (long)B_*d_, d_, d_, 1.f, 1);
            ln_k<<<P_*B_, 128, 0, s0>>>(ptmp, ppa + (long)l*B_*d_, (long)L_*B_*d_, ph,
                ln_act_g + (long)l*d_, ln_act_b + (long)l*d_, (long)L_*d_, d_);
        }

        gemm3_k<1,0,true><<<dim3(12, 1, M_), 512, 0, s0>>>(ph, 0, 0,
            out_w, (long)D_*D_, out_b, (long)D_, nullptr, 0,
            poutpre, (long)B_*D_, D_, D_, 1.f, 0);
        ln_k<<<M_*B_, 128, 0, s0>>>(poutpre, pmem, (long)B_*D_, nullptr,
            ln_out_g, ln_out_b, (long)D_, D_);
    }

    cudaMemcpyAsync(d_out, pmem, sizeof(float)*M_*B_*D_, cudaMemcpyDeviceToDevice, s0);
}

// round 14
// speedup vs baseline: 1.3783x; 1.0447x over previous
#include <cuda_runtime.h>
#include <cstdint>
#include <math.h>

// Problem dims
#define T_ 8
#define B_ 32
#define D_ 768
#define M_ 8
#define S_ 2
#define L_ 2
#define H_ 8
#define HD_ 96
#define d_ 384
#define P_ 16          // M_*S_
#define U_ 32          // P_*L_

typedef unsigned long long u64;

// ---------------- device state / scratch ----------------
__device__ float g_mem[M_*B_*D_];
__device__ float g_qall[(long)M_*T_*B_*D_];
__device__ float g_qk[(long)M_*H_*T_*B_*D_];
__device__ float g_wmem[(long)M_*H_*B_*D_];
__device__ float g_o[M_*B_*D_];
__device__ float g_h[P_*B_*d_];
__device__ float g_pa[U_*B_*d_];
__device__ float g_pr[U_*B_*d_];
__device__ float g_dp[U_*B_*d_];
__device__ float g_sr[U_*B_*d_];
__device__ float g_gb[U_*B_*d_];
__device__ float g_W [(long)U_*d_*d_];
__device__ float g_Wr[(long)U_*d_*d_];
__device__ float g_t1[U_*B_*d_];
__device__ float g_nt[U_*B_*3*d_];
__device__ float g_mod[U_*B_*d_];
__device__ float g_asm[2*U_*B_*d_];
__device__ float g_C[(long)2*U_*d_*d_];
__device__ float g_tmp[U_*B_*d_];
__device__ float g_outpre[M_*B_*D_];

// ---------------- f32x2 helpers ----------------
__device__ __forceinline__ u64 pack2(float x, float y) {
    u64 r;
    asm("mov.b64 %0, {%1, %2};" : "=l"(r) : "f"(x), "f"(y));
    return r;
}
__device__ __forceinline__ void fma2(u64& d, u64 a, u64 b) {
    asm("fma.rn.f32x2 %0, %1, %2, %0;" : "+l"(d) : "l"(a), "l"(b));
}
__device__ __forceinline__ void add2(u64& d, u64 o) {
    asm("add.rn.f32x2 %0, %0, %1;" : "+l"(d) : "l"(o));
}
__device__ __forceinline__ float2 unpack2(u64 v) {
    float2 f;
    asm("mov.b64 {%0, %1}, %2;" : "=f"(f.x), "=f"(f.y) : "l"(v));
    return f;
}
__device__ __forceinline__ float wsum(float v) {
    #pragma unroll
    for (int o = 16; o > 0; o >>= 1) v += __shfl_xor_sync(0xffffffffu, v, o);
    return v;
}
__device__ __forceinline__ float wmax(float v) {
    #pragma unroll
    for (int o = 16; o > 0; o >>= 1) v = fmaxf(v, __shfl_xor_sync(0xffffffffu, v, o));
    return v;
}

#define AS_STRIDE 36
#define BS_STRIDE 68

// ---------------- gemm2_k: R4-proven BM32 4x4 tile, 128 threads --------------
template<int AMODE, bool TRANSA, bool TRANSB>
__global__ __launch_bounds__(128) void gemm2_k(
                        const float* __restrict__ A, long aB, int lda,
                        const float* __restrict__ W, long wB, int zwrap, long wB2,
                        const float* __restrict__ bias, long bB,
                        float* __restrict__ C, long cB,
                        int N, int K, float scale)
{
    __shared__ float As[16*AS_STRIDE];
    __shared__ float Bs[16*BS_STRIDE];
    const int tid = threadIdx.x;
    const int tx = tid & 15;
    const int ty = tid >> 4;
    const int z = blockIdx.z;
    const float* Ab;
    if (AMODE == 2) Ab = A + (long)(z >> 3)*aB + (long)(z & 7)*96;
    else            Ab = A + (long)z*aB;
    const float* Wb;
    if (wB2) Wb = W + (long)(z >> 3)*wB + (long)(z & 7)*wB2;
    else     Wb = W + (long)(zwrap ? (z % zwrap) : z)*wB;
    const int row0 = blockIdx.y*32, col0 = blockIdx.x*64;

    u64 acc[4][2];
    #pragma unroll
    for (int r = 0; r < 4; r++) { acc[r][0] = 0ull; acc[r][1] = 0ull; }

    for (int k0 = 0; k0 < K; k0 += 16) {
        if (TRANSA) {
            int kk = tid >> 3, r4 = (tid & 7)*4;
            float4 av = *(const float4*)&Ab[(long)(k0 + kk)*lda + row0 + r4];
            *(float4*)&As[kk*AS_STRIDE + r4] = av;
        } else {
            int r = tid >> 2, kc = (tid & 3)*4;
            float4 av = *(const float4*)&Ab[(long)(row0 + r)*lda + k0 + kc];
            As[(kc+0)*AS_STRIDE + r] = av.x;
            As[(kc+1)*AS_STRIDE + r] = av.y;
            As[(kc+2)*AS_STRIDE + r] = av.z;
            As[(kc+3)*AS_STRIDE + r] = av.w;
        }
        #pragma unroll
        for (int it = 0; it < 2; it++) {
            int e = tid + it*128;
            if (TRANSB) {
                int j = e >> 2, kc = (e & 3)*4;
                float4 wv = *(const float4*)&Wb[(long)(col0 + j)*K + k0 + kc];
                Bs[(kc+0)*BS_STRIDE + j] = wv.x;
                Bs[(kc+1)*BS_STRIDE + j] = wv.y;
                Bs[(kc+2)*BS_STRIDE + j] = wv.z;
                Bs[(kc+3)*BS_STRIDE + j] = wv.w;
            } else {
                int kk = e >> 4, j4 = (e & 15)*4;
                float4 wv = *(const float4*)&Wb[(long)(k0 + kk)*N + col0 + j4];
                *(float4*)&Bs[kk*BS_STRIDE + j4] = wv;
            }
        }
        __syncthreads();
        #pragma unroll
        for (int kk = 0; kk < 16; kk++) {
            float4 a = *(const float4*)&As[kk*AS_STRIDE + ty*4];
            u64 b0 = *(const u64*)&Bs[kk*BS_STRIDE + tx*4];
            u64 b1 = *(const u64*)&Bs[kk*BS_STRIDE + tx*4 + 2];
            u64 a0 = pack2(a.x, a.x);
            u64 a1 = pack2(a.y, a.y);
            u64 a2 = pack2(a.z, a.z);
            u64 a3 = pack2(a.w, a.w);
            fma2(acc[0][0], a0, b0); fma2(acc[0][1], a0, b1);
            fma2(acc[1][0], a1, b0); fma2(acc[1][1], a1, b1);
            fma2(acc[2][0], a2, b0); fma2(acc[2][1], a2, b1);
            fma2(acc[3][0], a3, b0); fma2(acc[3][1], a3, b1);
        }
        __syncthreads();
    }

    float* Cb = C + (long)z*cB;
    const int colb = col0 + tx*4;
    #pragma unroll
    for (int r = 0; r < 4; r++) {
        int row = row0 + ty*4 + r;
        float2 v0 = unpack2(acc[r][0]);
        float2 v1 = unpack2(acc[r][1]);
        float v[4] = {v0.x, v0.y, v1.x, v1.y};
        #pragma unroll
        for (int c = 0; c < 4; c++) {
            if (bias) v[c] += bias[(long)z*bB + colb + c];
            v[c] *= scale;
        }
        *(float4*)&Cb[(long)row*N + colb] = make_float4(v[0], v[1], v[2], v[3]);
    }
}

// ---------------- gemm3_k: intra-block split-K, 4 k-groups, 512 threads ------
template<int AMODE, int CMODE, bool TRANSB>
__global__ __launch_bounds__(512) void gemm3_k(
                        const float* __restrict__ A, long aB, int lda,
                        const float* __restrict__ W, long wB,
                        const float* __restrict__ bias, long bB,
                        const float* __restrict__ add, long adB,
                        float* __restrict__ C, long cB,
                        int N, int K, float scale, int relu)
{
    __shared__ float As[4][16*AS_STRIDE];
    __shared__ float Bs[4][16*BS_STRIDE];
    __shared__ u64 red[2][128*8];
    const int tid = threadIdx.x;
    const int kg = tid >> 7;
    const int t = tid & 127;
    const int tx = t & 15;
    const int ty = t >> 4;
    const int z = blockIdx.z;
    const float* Ab = A + (long)z*aB;
    const float* Wb = W + (long)z*wB;
    const int row0 = blockIdx.y*32, col0 = blockIdx.x*64;

    u64 acc[4][2];
    #pragma unroll
    for (int r = 0; r < 4; r++) { acc[r][0] = 0ull; acc[r][1] = 0ull; }

    for (int k0 = kg*16; k0 < K; k0 += 64) {
        {
            int r = t >> 2, kc = (t & 3)*4;
            float4 av;
            if (AMODE == 1) {
                int k = k0 + kc; int sh = k / d_, kr = k % d_;
                av = *(const float4*)&A[(((long)z*2 + sh)*B_ + row0 + r)*d_ + kr];
            } else {
                av = *(const float4*)&Ab[(long)(row0 + r)*lda + k0 + kc];
            }
            As[kg][(kc+0)*AS_STRIDE + r] = av.x;
            As[kg][(kc+1)*AS_STRIDE + r] = av.y;
            As[kg][(kc+2)*AS_STRIDE + r] = av.z;
            As[kg][(kc+3)*AS_STRIDE + r] = av.w;
        }
        #pragma unroll
        for (int it = 0; it < 2; it++) {
            int e = t + it*128;
            if (TRANSB) {
                int j = e >> 2, kc = (e & 3)*4;
                float4 wv = *(const float4*)&Wb[(long)(col0 + j)*K + k0 + kc];
                Bs[kg][(kc+0)*BS_STRIDE + j] = wv.x;
                Bs[kg][(kc+1)*BS_STRIDE + j] = wv.y;
                Bs[kg][(kc+2)*BS_STRIDE + j] = wv.z;
                Bs[kg][(kc+3)*BS_STRIDE + j] = wv.w;
            } else {
                int kk = e >> 4, j4 = (e & 15)*4;
                float4 wv = *(const float4*)&Wb[(long)(k0 + kk)*N + col0 + j4];
                *(float4*)&Bs[kg][kk*BS_STRIDE + j4] = wv;
            }
        }
        __syncthreads();
        #pragma unroll
        for (int kk = 0; kk < 16; kk++) {
            float4 a = *(const float4*)&As[kg][kk*AS_STRIDE + ty*4];
            u64 b0 = *(const u64*)&Bs[kg][kk*BS_STRIDE + tx*4];
            u64 b1 = *(const u64*)&Bs[kg][kk*BS_STRIDE + tx*4 + 2];
            u64 a0 = pack2(a.x, a.x);
            u64 a1 = pack2(a.y, a.y);
            u64 a2 = pack2(a.z, a.z);
            u64 a3 = pack2(a.w, a.w);
            fma2(acc[0][0], a0, b0); fma2(acc[0][1], a0, b1);
            fma2(acc[1][0], a1, b0); fma2(acc[1][1], a1, b1);
            fma2(acc[2][0], a2, b0); fma2(acc[2][1], a2, b1);
            fma2(acc[3][0], a3, b0); fma2(acc[3][1], a3, b1);
        }
        __syncthreads();
    }

    if (kg & 1) {
        #pragma unroll
        for (int r = 0; r < 4; r++) {
            red[kg >> 1][(r*2 + 0)*128 + t] = acc[r][0];
            red[kg >> 1][(r*2 + 1)*128 + t] = acc[r][1];
        }
    }
    __syncthreads();
    if (!(kg & 1)) {
        #pragma unroll
        for (int r = 0; r < 4; r++) {
            add2(acc[r][0], red[kg >> 1][(r*2 + 0)*128 + t]);
            add2(acc[r][1], red[kg >> 1][(r*2 + 1)*128 + t]);
        }
    }
    __syncthreads();
    if (kg == 2) {
        #pragma unroll
        for (int r = 0; r < 4; r++) {
            red[0][(r*2 + 0)*128 + t] = acc[r][0];
            red[0][(r*2 + 1)*128 + t] = acc[r][1];
        }
    }
    __syncthreads();
    if (kg == 0) {
        #pragma unroll
        for (int r = 0; r < 4; r++) {
            add2(acc[r][0], red[0][(r*2 + 0)*128 + t]);
            add2(acc[r][1], red[0][(r*2 + 1)*128 + t]);
        }
        float* Cb = C + (long)z*cB;
        const int colb = col0 + tx*4;
        #pragma unroll
        for (int r = 0; r < 4; r++) {
            int row = row0 + ty*4 + r;
            float2 v0 = unpack2(acc[r][0]);
            float2 v1 = unpack2(acc[r][1]);
            float v[4] = {v0.x, v0.y, v1.x, v1.y};
            #pragma unroll
            for (int c = 0; c < 4; c++) {
                if (bias) v[c] += bias[(long)z*bB + colb + c];
                v[c] *= scale;
                if (add)  v[c] += add[(long)z*adB + (long)row*N + colb + c];
                if (relu) v[c] = fmaxf(v[c], 0.f);
            }
            if (CMODE) {
                int sh = colb / d_, jr = colb % d_;
                float* dst = C + (((long)z*2 + sh)*B_ + row)*d_ + jr;
                *(float4*)dst = make_float4(v[0], v[1], v[2], v[3]);
            } else {
                *(float4*)&Cb[(long)row*N + colb] = make_float4(v[0], v[1], v[2], v[3]);
            }
        }
    }
}

// ---------------- fused scores + softmax + weighted-mem  ---------------------
__global__ __launch_bounds__(256) void wmem_k(int t)
{
    int b = blockIdx.x, m = blockIdx.y;
    int tid = threadIdx.x;
    int w = tid >> 5, lane = tid & 31;
    __shared__ float memsh[M_*D_];
    __shared__ float scr[H_*M_];

    #pragma unroll
    for (int i = 0; i < 6; i++) {
        int fe = tid + i*256;
        int s = fe / 192, j4 = (fe % 192)*4;
        *(float4*)&memsh[s*D_ + j4] = *(const float4*)&g_mem[((long)s*B_ + b)*D_ + j4];
    }
    __syncthreads();

    const float* qkrow = g_qk + (((long)(m*H_ + w))*T_*B_ + t*B_ + b)*D_;
    float qv[24];
    #pragma unroll
    for (int i = 0; i < 24; i++) qv[i] = qkrow[lane + i*32];

    for (int s = 0; s < M_; s++) {
        float p = 0.f;
        #pragma unroll
        for (int i = 0; i < 24; i++) p += qv[i]*memsh[s*D_ + lane + i*32];
        p = wsum(p);
        if (lane == 0) scr[w*M_ + s] = p;
    }
    __syncwarp();

    float a[M_];
    float mx = -1e30f;
    #pragma unroll
    for (int s = 0; s < M_; s++) mx = fmaxf(mx, scr[w*M_ + s]);
    float sum = 0.f;
    #pragma unroll
    for (int s = 0; s < M_; s++) { a[s] = __expf(scr[w*M_ + s] - mx); sum += a[s]; }
    float inv = 1.f / sum;
    #pragma unroll
    for (int s = 0; s < M_; s++) a[s] *= inv;

    float* dst = g_wmem + (((long)(m*H_ + w))*B_ + b)*D_;
    #pragma unroll
    for (int i = 0; i < 24; i++) {
        int j = lane + i*32;
        float acc = 0.f;
        #pragma unroll
        for (int s = 0; s < M_; s++) acc += a[s]*memsh[s*D_ + j];
        dst[j] = acc;
    }
}

// ---------------- per-head V projection ----------------
__global__ __launch_bounds__(128) void attnv_k(const float* __restrict__ w,
                                               const float* __restrict__ bias)
{
    __shared__ float As[16*36];
    __shared__ float Bs[16*36];
    const int tid = threadIdx.x;
    const int tx = tid & 7;
    const int ty = tid >> 3;
    const int z = blockIdx.z, m = z >> 3, h = z & 7;
    const int col0 = blockIdx.x*32;
    const float* Ab = g_wmem + (long)z*B_*D_;
    const float* Wb = w + (long)m*3*D_*D_ + (long)(2*D_ + h*HD_)*D_;

    u64 acc[2][2];
    acc[0][0] = acc[0][1] = acc[1][0] = acc[1][1] = 0ull;

    for (int k0 = 0; k0 < D_; k0 += 16) {
        {
            int r = tid >> 2, kc = (tid & 3)*4;
            float4 av = *(const float4*)&Ab[(long)r*D_ + k0 + kc];
            As[(kc+0)*36 + r] = av.x;
            As[(kc+1)*36 + r] = av.y;
            As[(kc+2)*36 + r] = av.z;
            As[(kc+3)*36 + r] = av.w;
        }
        {
            int j = tid >> 2, kc = (tid & 3)*4;
            float4 wv = *(const float4*)&Wb[(long)(col0 + j)*D_ + k0 + kc];
            Bs[(kc+0)*36 + j] = wv.x;
            Bs[(kc+1)*36 + j] = wv.y;
            Bs[(kc+2)*36 + j] = wv.z;
            Bs[(kc+3)*36 + j] = wv.w;
        }
        __syncthreads();
        #pragma unroll
        for (int kk = 0; kk < 16; kk++) {
            float2 a = *(const float2*)&As[kk*36 + ty*2];
            u64 b0 = *(const u64*)&Bs[kk*36 + tx*4];
            u64 b1 = *(const u64*)&Bs[kk*36 + tx*4 + 2];
            u64 a0 = pack2(a.x, a.x);
            u64 a1 = pack2(a.y, a.y);
            fma2(acc[0][0], a0, b0); fma2(acc[0][1], a0, b1);
            fma2(acc[1][0], a1, b0); fma2(acc[1][1], a1, b1);
        }
        __syncthreads();
    }

    const float* bb = bias + (long)m*3*D_ + 2*D_ + h*HD_ + col0 + tx*4;
    #pragma unroll
    for (int r = 0; r < 2; r++) {
        int row = ty*2 + r;
        float2 v0 = unpack2(acc[r][0]);
        float2 v1 = unpack2(acc[r][1]);
        float4 v = make_float4(v0.x + bb[0], v0.y + bb[1], v1.x + bb[2], v1.y + bb[3]);
        *(float4*)&g_o[((long)m*B_ + row)*D_ + h*HD_ + col0 + tx*4] = v;
    }
}

// ---------------- plastic layer kernels ----------------
__global__ void gates_k(const float* __restrict__ alpha)
{
    int idx = blockIdx.x*256 + threadIdx.x;
    if (idx >= U_*B_*d_) return;
    int j = idx % d_; int b = (idx/d_) % B_; int u = idx/(B_*d_);
    const float* nt = g_nt + ((long)(u*B_ + b))*3*d_ + j*3;
    float pd = nt[0], ps = nt[1], pg = nt[2];
    float inv = 1.f / fmaxf(ps, 1e-6f);
    float dpv = tanhf(g_dp[idx] + pd*inv);
    float srv = 1.f/(1.f + __expf(-(g_sr[idx] + ps)));
    float gbv = 1.f/(1.f + __expf(-(g_gb[idx] + pg*inv)));
    g_dp[idx] = dpv; g_sr[idx] = srv; g_gb[idx] = gbv;
    g_mod[idx] = alpha[(long)u*d_ + j] * dpv * srv;
}

// warp-per-row softmax: grid (U_*B_/4, 2), 128 threads
__global__ __launch_bounds__(128) void rsm_k()
{
    int w = threadIdx.x >> 5, lane = threadIdx.x & 31;
    int row = blockIdx.x*4 + w;
    int which = blockIdx.y;
    const float* src = (which ? g_pr : g_pa) + (long)row*d_;
    float* dst = g_asm + (long)which*U_*B_*d_ + (long)row*d_;
    float v[12];
    float mx = -1e30f;
    #pragma unroll
    for (int i = 0; i < 12; i++) { v[i] = src[lane + i*32]; mx = fmaxf(mx, v[i]); }
    mx = wmax(mx);
    float sum = 0.f;
    #pragma unroll
    for (int i = 0; i < 12; i++) { v[i] = __expf(v[i] - mx); sum += v[i]; }
    sum = wsum(sum);
    float inv = 1.f / sum;
    #pragma unroll
    for (int i = 0; i < 12; i++) dst[lane + i*32] = v[i]*inv;
}

// warp-per-row W update (incl. in-warp sd): grid (d_/4, U_), 128 threads
__global__ __launch_bounds__(128) void wupd_k(const float* __restrict__ decay, int which)
{
    int w = threadIdx.x >> 5, lane = threadIdx.x & 31;
    int i = blockIdx.x*4 + w, u = blockIdx.y;
    float* Wp = (which ? g_Wr : g_W) + ((long)u*d_ + i)*d_;
    const float* Cp = g_C + ((long)(which*U_ + u)*d_ + i)*d_;
    // sd: mean over b of gb, sigmoid, * decay  (lane b)
    float gv = g_gb[((long)u*B_ + lane)*d_ + i];
    gv = wsum(gv);
    float sd = decay[(long)u*d_ + i] * (1.f/(1.f + __expf(-gv*(1.f/B_))));
    float om = 1.f - sd;
    float wv[12];
    float mx = -1e30f;
    #pragma unroll
    for (int k = 0; k < 12; k++) { wv[k] = Wp[lane + k*32]; mx = fmaxf(mx, wv[k]); }
    mx = wmax(mx);
    float ev[12];
    float sum = 0.f;
    #pragma unroll
    for (int k = 0; k < 12; k++) { ev[k] = __expf(wv[k] - mx); sum += ev[k]; }
    sum = wsum(sum);
    float inv = 1.f / sum;
    #pragma unroll
    for (int k = 0; k < 12; k++)
        Wp[lane + k*32] = wv[k]*om + ev[k]*inv*Cp[lane + k*32];
}

// ---------------- LayerNorm (warp-per-row): grid rows/4, 128 threads ---------
__global__ __launch_bounds__(128) void ln_k(const float* __restrict__ in,
                     float* __restrict__ out1, long o1Group,
                     float* __restrict__ out2,
                     const float* __restrict__ gam, const float* __restrict__ bet,
                     long gGroup, int N)
{
    int w = threadIdx.x >> 5, lane = threadIdx.x & 31;
    int row = blockIdx.x*4 + w;
    int grp = row / B_, rb = row % B_;
    const float* x = in + (long)row*N;
    int nper = N / 32;   // 12 or 24
    float vals[24];
    float s = 0.f;
    for (int t = 0; t < nper; t++) { vals[t] = x[lane + t*32]; s += vals[t]; }
    s = wsum(s);
    float mu = s / N;
    float sq = 0.f;
    for (int t = 0; t < nper; t++) { float dv = vals[t] - mu; sq += dv*dv; }
    sq = wsum(sq);
    float rstd = rsqrtf(sq / N + 1e-5f);
    float* o1 = out1 + (long)grp*o1Group + (long)rb*N;
    const float* gp = gam + (long)grp*gGroup;
    const float* bp = bet + (long)grp*gGroup;
    for (int t = 0; t < nper; t++) {
        int j = lane + t*32;
        float y = (vals[t] - mu)*rstd*gp[j] + bp[j];
        o1[j] = y;
        if (out2) out2[(long)row*N + j] = y;
    }
}

__global__ void clear_k()
{
    long idx = (long)blockIdx.x*256 + threadIdx.x;
    if (idx < (long)U_*B_*d_) {
        g_pa[idx] = 0.f; g_pr[idx] = 0.f; g_dp[idx] = 0.f; g_sr[idx] = 0.f; g_gb[idx] = 0.f;
    }
}

// ---------------- host launcher ----------------
extern "C" void kernel_launch(void* const* d_in, const int* in_sizes, int n_in,
                              void* d_out, int out_size)
{
    const float* x          = (const float*)d_in[0];
    const float* mem0       = (const float*)d_in[1];
    const float* attn_in_w  = (const float*)d_in[2];
    const float* attn_in_b  = (const float*)d_in[3];
    const float* attn_out_w = (const float*)d_in[4];
    const float* attn_out_b = (const float*)d_in[5];
    const float* heb_w      = (const float*)d_in[6];
    const float* heb_rw     = (const float*)d_in[7];
    const float* alpha      = (const float*)d_in[8];
    const float* decay      = (const float*)d_in[9];
    const float* ln_act_g   = (const float*)d_in[10];
    const float* ln_act_b   = (const float*)d_in[11];
    const float* ln_rec_g   = (const float*)d_in[12];
    const float* ln_rec_b   = (const float*)d_in[13];
    const float* pred_w1    = (const float*)d_in[14];
    const float* pred_b1    = (const float*)d_in[15];
    const float* pred_w2    = (const float*)d_in[16];
    const float* pred_b2    = (const float*)d_in[17];
    const float* out_w      = (const float*)d_in[18];
    const float* out_b      = (const float*)d_in[19];
    const float* ln_out_g   = (const float*)d_in[20];
    const float* ln_out_b   = (const float*)d_in[21];

    float *pmem, *pqall, *pqk, *po, *ph, *ppa, *ppr, *pt1, *pnt, *ptmp,
          *poutpre, *pW, *pWr, *pasm, *pmod, *pC;
    cudaGetSymbolAddress((void**)&pmem,    g_mem);
    cudaGetSymbolAddress((void**)&pqall,   g_qall);
    cudaGetSymbolAddress((void**)&pqk,     g_qk);
    cudaGetSymbolAddress((void**)&po,      g_o);
    cudaGetSymbolAddress((void**)&ph,      g_h);
    cudaGetSymbolAddress((void**)&ppa,     g_pa);
    cudaGetSymbolAddress((void**)&ppr,     g_pr);
    cudaGetSymbolAddress((void**)&pt1,     g_t1);
    cudaGetSymbolAddress((void**)&pnt,     g_nt);
    cudaGetSymbolAddress((void**)&ptmp,    g_tmp);
    cudaGetSymbolAddress((void**)&poutpre, g_outpre);
    cudaGetSymbolAddress((void**)&pW,      g_W);
    cudaGetSymbolAddress((void**)&pWr,     g_Wr);
    cudaGetSymbolAddress((void**)&pasm,    g_asm);
    cudaGetSymbolAddress((void**)&pmod,    g_mod);
    cudaGetSymbolAddress((void**)&pC,      g_C);

    static cudaStream_t s1 = nullptr, s2 = nullptr;
    static cudaEvent_t evFork = nullptr, evHeb = nullptr, evGates = nullptr, evW = nullptr;
    if (!s1) {
        cudaStreamCreateWithFlags(&s1, cudaStreamNonBlocking);
        cudaStreamCreateWithFlags(&s2, cudaStreamNonBlocking);
        cudaEventCreateWithFlags(&evFork,  cudaEventDisableTiming);
        cudaEventCreateWithFlags(&evHeb,   cudaEventDisableTiming);
        cudaEventCreateWithFlags(&evGates, cudaEventDisableTiming);
        cudaEventCreateWithFlags(&evW,     cudaEventDisableTiming);
    }
    cudaStream_t s0 = 0;

    const float qscale = 1.f / sqrtf((float)HD_);

    // init state (s0)
    cudaMemcpyAsync(pW,  heb_w,  sizeof(float)*(long)U_*d_*d_, cudaMemcpyDeviceToDevice, s0);
    cudaMemcpyAsync(pWr, heb_rw, sizeof(float)*(long)U_*d_*d_, cudaMemcpyDeviceToDevice, s0);
    cudaMemcpyAsync(pmem, mem0,  sizeof(float)*M_*B_*D_,       cudaMemcpyDeviceToDevice, s0);
    clear_k<<<(U_*B_*d_ + 255)/256, 256, 0, s0>>>();

    // q for all timesteps, then qk = qh @ Wk (per head)
    gemm2_k<0,false,true><<<dim3(12, 8, M_), 128, 0, s0>>>(x, 0, D_,
        attn_in_w, (long)3*D_*D_, 0, 0, attn_in_b, (long)3*D_,
        pqall, (long)T_*B_*D_, D_, D_, qscale);
    gemm2_k<2,false,false><<<dim3(12, 8, M_*H_), 128, 0, s0>>>(pqall, (long)T_*B_*D_, D_,
        attn_in_w + (long)D_*D_, (long)3*D_*D_, 0, (long)HD_*D_,
        nullptr, 0,
        pqk, (long)T_*B_*D_, D_, HD_, 1.f);

    for (int t = 0; t < T_; t++) {
        cudaEventRecord(evFork, s0);
        cudaStreamWaitEvent(s1, evFork, 0);

        // ---- Hebbian chain on s1; W-half forked to s2 ----
        rsm_k<<<dim3(U_*B_/4, 2), 128, 0, s1>>>();
        gemm3_k<0,0,false><<<dim3(6, 1, U_), 512, 0, s1>>>(ppa, (long)B_*d_, d_,
            pred_w1, (long)d_*d_, pred_b1, (long)d_, nullptr, 0,
            pt1, (long)B_*d_, d_, d_, 1.f, 1);
        gemm3_k<0,0,false><<<dim3(18, 1, U_), 512, 0, s1>>>(pt1, (long)B_*d_, d_,
            pred_w2, (long)d_*3*d_, pred_b2, (long)3*d_, nullptr, 0,
            pnt, (long)B_*3*d_, 3*d_, d_, 1.f, 0);
        gates_k<<<(U_*B_*d_ + 255)/256, 256, 0, s1>>>(alpha);
        cudaEventRecord(evGates, s1);

        // s2: W-half (outer which=0 + wupd W) — joins at acts
        cudaStreamWaitEvent(s2, evGates, 0);
        gemm2_k<0,true,false><<<dim3(6, 12, U_), 128, 0, s2>>>(pasm, (long)B_*d_, d_,
            pmod, (long)B_*d_, 0, 0, nullptr, 0,
            pC, (long)d_*d_, d_, B_, 1.f/B_);
        wupd_k<<<dim3(d_/4, U_), 128, 0, s2>>>(decay, 0);
        cudaEventRecord(evW, s2);

        // s1: Wr-half (critical path to rec/pr)
        gemm2_k<0,true,false><<<dim3(6, 12, U_), 128, 0, s1>>>(pasm + (long)U_*B_*d_, (long)B_*d_, d_,
            pmod, (long)B_*d_, 0, 0, nullptr, 0,
            pC + (long)U_*d_*d_, (long)d_*d_, d_, B_, 1.f/B_);
        wupd_k<<<dim3(d_/4, U_), 128, 0, s1>>>(decay, 1);
        gemm3_k<0,0,false><<<dim3(6, 1, U_), 512, 0, s1>>>(ppa, (long)B_*d_, d_,
            pWr, (long)d_*d_, nullptr, 0, nullptr, 0,
            ptmp, (long)B_*d_, d_, d_, 1.f, 0);
        ln_k<<<U_*B_/4, 128, 0, s1>>>(ptmp, ppr, (long)B_*d_, nullptr,
            ln_rec_g, ln_rec_b, (long)d_, d_);
        cudaEventRecord(evHeb, s1);

        // ---- attention chain on s0 ----
        wmem_k<<<dim3(B_, M_), 256, 0, s0>>>(t);
        attnv_k<<<dim3(3, 1, M_*H_), 128, 0, s0>>>(attn_in_w, attn_in_b);
        gemm3_k<0,1,true><<<dim3(12, 1, M_), 512, 0, s0>>>(po, (long)B_*D_, D_,
            attn_out_w, (long)D_*D_, attn_out_b, (long)D_, nullptr, 0,
            ph, 0, D_, D_, 1.f, 0);

        cudaStreamWaitEvent(s0, evHeb, 0);
        cudaStreamWaitEvent(s0, evW, 0);

        for (int l = 0; l < L_; l++) {
            gemm3_k<0,0,false><<<dim3(6, 1, P_), 512, 0, s0>>>(ph, (long)B_*d_, d_,
                pW + (long)l*d_*d_, (long)L_*d_*d_, nullptr, 0,
                ppr + (long)l*B_*d_, (long)L_*B_*d_,
                ptmp, (long)B_*d_, d_, d_, 1.f, 1);
            ln_k<<<P_*B_/4, 128, 0, s0>>>(ptmp, ppa + (long)l*B_*d_, (long)L_*B_*d_, ph,
                ln_act_g + (long)l*d_, ln_act_b + (long)l*d_, (long)L_*d_, d_);
        }

        gemm3_k<1,0,true><<<dim3(12, 1, M_), 512, 0, s0>>>(ph, 0, 0,
            out_w, (long)D_*D_, out_b, (long)D_, nullptr, 0,
            poutpre, (long)B_*D_, D_, D_, 1.f, 0);
        ln_k<<<M_*B_/4, 128, 0, s0>>>(poutpre, pmem, (long)B_*D_, nullptr,
            ln_out_g, ln_out_b, (long)D_, D_);
    }

    cudaMemcpyAsync(d_out, pmem, sizeof(float)*M_*B_*D_, cudaMemcpyDeviceToDevice, s0);
}

// round 15
// speedup vs baseline: 1.3887x; 1.0075x over previous
#include <cuda_runtime.h>
#include <cstdint>
#include <math.h>

// Problem dims
#define T_ 8
#define B_ 32
#define D_ 768
#define M_ 8
#define S_ 2
#define L_ 2
#define H_ 8
#define HD_ 96
#define d_ 384
#define P_ 16          // M_*S_
#define U_ 32          // P_*L_

typedef unsigned long long u64;

// ---------------- device state / scratch ----------------
__device__ float g_mem[M_*B_*D_];
__device__ float g_qall[(long)M_*T_*B_*D_];
__device__ float g_qk[(long)M_*H_*T_*B_*D_];
__device__ float g_wmem[(long)M_*H_*B_*D_];
__device__ float g_o[M_*B_*D_];
__device__ float g_h[P_*B_*d_];
__device__ float g_pa[U_*B_*d_];
__device__ float g_pr[U_*B_*d_];
__device__ float g_dp[U_*B_*d_];
__device__ float g_sr[U_*B_*d_];
__device__ float g_gb[U_*B_*d_];
__device__ float g_W [(long)U_*d_*d_];
__device__ float g_Wr[(long)U_*d_*d_];
__device__ float g_t1[U_*B_*d_];
__device__ float g_nt[U_*B_*3*d_];
__device__ float g_mod[U_*B_*d_];
__device__ float g_asm[2*U_*B_*d_];
__device__ float g_C[(long)2*U_*d_*d_];
__device__ float g_tmp[U_*B_*d_];
__device__ float g_outpre[M_*B_*D_];

// ---------------- f32x2 helpers ----------------
__device__ __forceinline__ u64 pack2(float x, float y) {
    u64 r;
    asm("mov.b64 %0, {%1, %2};" : "=l"(r) : "f"(x), "f"(y));
    return r;
}
__device__ __forceinline__ void fma2(u64& d, u64 a, u64 b) {
    asm("fma.rn.f32x2 %0, %1, %2, %0;" : "+l"(d) : "l"(a), "l"(b));
}
__device__ __forceinline__ void add2(u64& d, u64 o) {
    asm("add.rn.f32x2 %0, %0, %1;" : "+l"(d) : "l"(o));
}
__device__ __forceinline__ float2 unpack2(u64 v) {
    float2 f;
    asm("mov.b64 {%0, %1}, %2;" : "=f"(f.x), "=f"(f.y) : "l"(v));
    return f;
}
__device__ __forceinline__ float wsum(float v) {
    #pragma unroll
    for (int o = 16; o > 0; o >>= 1) v += __shfl_xor_sync(0xffffffffu, v, o);
    return v;
}
__device__ __forceinline__ float wmax(float v) {
    #pragma unroll
    for (int o = 16; o > 0; o >>= 1) v = fmaxf(v, __shfl_xor_sync(0xffffffffu, v, o));
    return v;
}

#define AS_STRIDE 36
#define BS_STRIDE 68

// ---------------- gemm2_k: R4-proven BM32 4x4 tile, 128 threads --------------
template<int AMODE, bool TRANSA, bool TRANSB>
__global__ __launch_bounds__(128) void gemm2_k(
                        const float* __restrict__ A, long aB, int lda,
                        const float* __restrict__ W, long wB, int zwrap, long wB2,
                        const float* __restrict__ bias, long bB,
                        float* __restrict__ C, long cB,
                        int N, int K, float scale)
{
    __shared__ float As[16*AS_STRIDE];
    __shared__ float Bs[16*BS_STRIDE];
    const int tid = threadIdx.x;
    const int tx = tid & 15;
    const int ty = tid >> 4;
    const int z = blockIdx.z;
    const float* Ab;
    if (AMODE == 2) Ab = A + (long)(z >> 3)*aB + (long)(z & 7)*96;
    else            Ab = A + (long)z*aB;
    const float* Wb;
    if (wB2) Wb = W + (long)(z >> 3)*wB + (long)(z & 7)*wB2;
    else     Wb = W + (long)(zwrap ? (z % zwrap) : z)*wB;
    const int row0 = blockIdx.y*32, col0 = blockIdx.x*64;

    u64 acc[4][2];
    #pragma unroll
    for (int r = 0; r < 4; r++) { acc[r][0] = 0ull; acc[r][1] = 0ull; }

    for (int k0 = 0; k0 < K; k0 += 16) {
        if (TRANSA) {
            int kk = tid >> 3, r4 = (tid & 7)*4;
            float4 av = *(const float4*)&Ab[(long)(k0 + kk)*lda + row0 + r4];
            *(float4*)&As[kk*AS_STRIDE + r4] = av;
        } else {
            int r = tid >> 2, kc = (tid & 3)*4;
            float4 av = *(const float4*)&Ab[(long)(row0 + r)*lda + k0 + kc];
            As[(kc+0)*AS_STRIDE + r] = av.x;
            As[(kc+1)*AS_STRIDE + r] = av.y;
            As[(kc+2)*AS_STRIDE + r] = av.z;
            As[(kc+3)*AS_STRIDE + r] = av.w;
        }
        #pragma unroll
        for (int it = 0; it < 2; it++) {
            int e = tid + it*128;
            if (TRANSB) {
                int j = e >> 2, kc = (e & 3)*4;
                float4 wv = *(const float4*)&Wb[(long)(col0 + j)*K + k0 + kc];
                Bs[(kc+0)*BS_STRIDE + j] = wv.x;
                Bs[(kc+1)*BS_STRIDE + j] = wv.y;
                Bs[(kc+2)*BS_STRIDE + j] = wv.z;
                Bs[(kc+3)*BS_STRIDE + j] = wv.w;
            } else {
                int kk = e >> 4, j4 = (e & 15)*4;
                float4 wv = *(const float4*)&Wb[(long)(k0 + kk)*N + col0 + j4];
                *(float4*)&Bs[kk*BS_STRIDE + j4] = wv;
            }
        }
        __syncthreads();
        #pragma unroll
        for (int kk = 0; kk < 16; kk++) {
            float4 a = *(const float4*)&As[kk*AS_STRIDE + ty*4];
            u64 b0 = *(const u64*)&Bs[kk*BS_STRIDE + tx*4];
            u64 b1 = *(const u64*)&Bs[kk*BS_STRIDE + tx*4 + 2];
            u64 a0 = pack2(a.x, a.x);
            u64 a1 = pack2(a.y, a.y);
            u64 a2 = pack2(a.z, a.z);
            u64 a3 = pack2(a.w, a.w);
            fma2(acc[0][0], a0, b0); fma2(acc[0][1], a0, b1);
            fma2(acc[1][0], a1, b0); fma2(acc[1][1], a1, b1);
            fma2(acc[2][0], a2, b0); fma2(acc[2][1], a2, b1);
            fma2(acc[3][0], a3, b0); fma2(acc[3][1], a3, b1);
        }
        __syncthreads();
    }

    float* Cb = C + (long)z*cB;
    const int colb = col0 + tx*4;
    #pragma unroll
    for (int r = 0; r < 4; r++) {
        int row = row0 + ty*4 + r;
        float2 v0 = unpack2(acc[r][0]);
        float2 v1 = unpack2(acc[r][1]);
        float v[4] = {v0.x, v0.y, v1.x, v1.y};
        #pragma unroll
        for (int c = 0; c < 4; c++) {
            if (bias) v[c] += bias[(long)z*bB + colb + c];
            v[c] *= scale;
        }
        *(float4*)&Cb[(long)row*N + colb] = make_float4(v[0], v[1], v[2], v[3]);
    }
}

// ---------------- gemm3_k: intra-block split-K, 4 k-groups, 512 threads ------
template<int AMODE, int CMODE, bool TRANSB>
__global__ __launch_bounds__(512) void gemm3_k(
                        const float* __restrict__ A, long aB, int lda,
                        const float* __restrict__ W, long wB,
                        const float* __restrict__ bias, long bB,
                        const float* __restrict__ add, long adB,
                        float* __restrict__ C, long cB,
                        int N, int K, float scale, int relu)
{
    __shared__ float As[4][16*AS_STRIDE];
    __shared__ float Bs[4][16*BS_STRIDE];
    __shared__ u64 red[2][128*8];
    const int tid = threadIdx.x;
    const int kg = tid >> 7;
    const int t = tid & 127;
    const int tx = t & 15;
    const int ty = t >> 4;
    const int z = blockIdx.z;
    const float* Ab = A + (long)z*aB;
    const float* Wb = W + (long)z*wB;
    const int row0 = blockIdx.y*32, col0 = blockIdx.x*64;

    u64 acc[4][2];
    #pragma unroll
    for (int r = 0; r < 4; r++) { acc[r][0] = 0ull; acc[r][1] = 0ull; }

    for (int k0 = kg*16; k0 < K; k0 += 64) {
        {
            int r = t >> 2, kc = (t & 3)*4;
            float4 av;
            if (AMODE == 1) {
                int k = k0 + kc; int sh = k / d_, kr = k % d_;
                av = *(const float4*)&A[(((long)z*2 + sh)*B_ + row0 + r)*d_ + kr];
            } else {
                av = *(const float4*)&Ab[(long)(row0 + r)*lda + k0 + kc];
            }
            As[kg][(kc+0)*AS_STRIDE + r] = av.x;
            As[kg][(kc+1)*AS_STRIDE + r] = av.y;
            As[kg][(kc+2)*AS_STRIDE + r] = av.z;
            As[kg][(kc+3)*AS_STRIDE + r] = av.w;
        }
        #pragma unroll
        for (int it = 0; it < 2; it++) {
            int e = t + it*128;
            if (TRANSB) {
                int j = e >> 2, kc = (e & 3)*4;
                float4 wv = *(const float4*)&Wb[(long)(col0 + j)*K + k0 + kc];
                Bs[kg][(kc+0)*BS_STRIDE + j] = wv.x;
                Bs[kg][(kc+1)*BS_STRIDE + j] = wv.y;
                Bs[kg][(kc+2)*BS_STRIDE + j] = wv.z;
                Bs[kg][(kc+3)*BS_STRIDE + j] = wv.w;
            } else {
                int kk = e >> 4, j4 = (e & 15)*4;
                float4 wv = *(const float4*)&Wb[(long)(k0 + kk)*N + col0 + j4];
                *(float4*)&Bs[kg][kk*BS_STRIDE + j4] = wv;
            }
        }
        __syncthreads();
        #pragma unroll
        for (int kk = 0; kk < 16; kk++) {
            float4 a = *(const float4*)&As[kg][kk*AS_STRIDE + ty*4];
            u64 b0 = *(const u64*)&Bs[kg][kk*BS_STRIDE + tx*4];
            u64 b1 = *(const u64*)&Bs[kg][kk*BS_STRIDE + tx*4 + 2];
            u64 a0 = pack2(a.x, a.x);
            u64 a1 = pack2(a.y, a.y);
            u64 a2 = pack2(a.z, a.z);
            u64 a3 = pack2(a.w, a.w);
            fma2(acc[0][0], a0, b0); fma2(acc[0][1], a0, b1);
            fma2(acc[1][0], a1, b0); fma2(acc[1][1], a1, b1);
            fma2(acc[2][0], a2, b0); fma2(acc[2][1], a2, b1);
            fma2(acc[3][0], a3, b0); fma2(acc[3][1], a3, b1);
        }
        __syncthreads();
    }

    if (kg & 1) {
        #pragma unroll
        for (int r = 0; r < 4; r++) {
            red[kg >> 1][(r*2 + 0)*128 + t] = acc[r][0];
            red[kg >> 1][(r*2 + 1)*128 + t] = acc[r][1];
        }
    }
    __syncthreads();
    if (!(kg & 1)) {
        #pragma unroll
        for (int r = 0; r < 4; r++) {
            add2(acc[r][0], red[kg >> 1][(r*2 + 0)*128 + t]);
            add2(acc[r][1], red[kg >> 1][(r*2 + 1)*128 + t]);
        }
    }
    __syncthreads();
    if (kg == 2) {
        #pragma unroll
        for (int r = 0; r < 4; r++) {
            red[0][(r*2 + 0)*128 + t] = acc[r][0];
            red[0][(r*2 + 1)*128 + t] = acc[r][1];
        }
    }
    __syncthreads();
    if (kg == 0) {
        #pragma unroll
        for (int r = 0; r < 4; r++) {
            add2(acc[r][0], red[0][(r*2 + 0)*128 + t]);
            add2(acc[r][1], red[0][(r*2 + 1)*128 + t]);
        }
        float* Cb = C + (long)z*cB;
        const int colb = col0 + tx*4;
        #pragma unroll
        for (int r = 0; r < 4; r++) {
            int row = row0 + ty*4 + r;
            float2 v0 = unpack2(acc[r][0]);
            float2 v1 = unpack2(acc[r][1]);
            float v[4] = {v0.x, v0.y, v1.x, v1.y};
            #pragma unroll
            for (int c = 0; c < 4; c++) {
                if (bias) v[c] += bias[(long)z*bB + colb + c];
                v[c] *= scale;
                if (add)  v[c] += add[(long)z*adB + (long)row*N + colb + c];
                if (relu) v[c] = fmaxf(v[c], 0.f);
            }
            if (CMODE) {
                int sh = colb / d_, jr = colb % d_;
                float* dst = C + (((long)z*2 + sh)*B_ + row)*d_ + jr;
                *(float4*)dst = make_float4(v[0], v[1], v[2], v[3]);
            } else {
                *(float4*)&Cb[(long)row*N + colb] = make_float4(v[0], v[1], v[2], v[3]);
            }
        }
    }
}

// ---------------- fused scores + softmax + weighted-mem  ---------------------
__global__ __launch_bounds__(256) void wmem_k(int t)
{
    int b = blockIdx.x, m = blockIdx.y;
    int tid = threadIdx.x;
    int w = tid >> 5, lane = tid & 31;
    __shared__ float memsh[M_*D_];
    __shared__ float scr[H_*M_];

    #pragma unroll
    for (int i = 0; i < 6; i++) {
        int fe = tid + i*256;
        int s = fe / 192, j4 = (fe % 192)*4;
        *(float4*)&memsh[s*D_ + j4] = *(const float4*)&g_mem[((long)s*B_ + b)*D_ + j4];
    }
    __syncthreads();

    const float* qkrow = g_qk + (((long)(m*H_ + w))*T_*B_ + t*B_ + b)*D_;
    float qv[24];
    #pragma unroll
    for (int i = 0; i < 24; i++) qv[i] = qkrow[lane + i*32];

    for (int s = 0; s < M_; s++) {
        float p = 0.f;
        #pragma unroll
        for (int i = 0; i < 24; i++) p += qv[i]*memsh[s*D_ + lane + i*32];
        p = wsum(p);
        if (lane == 0) scr[w*M_ + s] = p;
    }
    __syncwarp();

    float a[M_];
    float mx = -1e30f;
    #pragma unroll
    for (int s = 0; s < M_; s++) mx = fmaxf(mx, scr[w*M_ + s]);
    float sum = 0.f;
    #pragma unroll
    for (int s = 0; s < M_; s++) { a[s] = __expf(scr[w*M_ + s] - mx); sum += a[s]; }
    float inv = 1.f / sum;
    #pragma unroll
    for (int s = 0; s < M_; s++) a[s] *= inv;

    float* dst = g_wmem + (((long)(m*H_ + w))*B_ + b)*D_;
    #pragma unroll
    for (int i = 0; i < 24; i++) {
        int j = lane + i*32;
        float acc = 0.f;
        #pragma unroll
        for (int s = 0; s < M_; s++) acc += a[s]*memsh[s*D_ + j];
        dst[j] = acc;
    }
}

// ---------------- per-head V projection ----------------
__global__ __launch_bounds__(128) void attnv_k(const float* __restrict__ w,
                                               const float* __restrict__ bias)
{
    __shared__ float As[16*36];
    __shared__ float Bs[16*36];
    const int tid = threadIdx.x;
    const int tx = tid & 7;
    const int ty = tid >> 3;
    const int z = blockIdx.z, m = z >> 3, h = z & 7;
    const int col0 = blockIdx.x*32;
    const float* Ab = g_wmem + (long)z*B_*D_;
    const float* Wb = w + (long)m*3*D_*D_ + (long)(2*D_ + h*HD_)*D_;

    u64 acc[2][2];
    acc[0][0] = acc[0][1] = acc[1][0] = acc[1][1] = 0ull;

    for (int k0 = 0; k0 < D_; k0 += 16) {
        {
            int r = tid >> 2, kc = (tid & 3)*4;
            float4 av = *(const float4*)&Ab[(long)r*D_ + k0 + kc];
            As[(kc+0)*36 + r] = av.x;
            As[(kc+1)*36 + r] = av.y;
            As[(kc+2)*36 + r] = av.z;
            As[(kc+3)*36 + r] = av.w;
        }
        {
            int j = tid >> 2, kc = (tid & 3)*4;
            float4 wv = *(const float4*)&Wb[(long)(col0 + j)*D_ + k0 + kc];
            Bs[(kc+0)*36 + j] = wv.x;
            Bs[(kc+1)*36 + j] = wv.y;
            Bs[(kc+2)*36 + j] = wv.z;
            Bs[(kc+3)*36 + j] = wv.w;
        }
        __syncthreads();
        #pragma unroll
        for (int kk = 0; kk < 16; kk++) {
            float2 a = *(const float2*)&As[kk*36 + ty*2];
            u64 b0 = *(const u64*)&Bs[kk*36 + tx*4];
            u64 b1 = *(const u64*)&Bs[kk*36 + tx*4 + 2];
            u64 a0 = pack2(a.x, a.x);
            u64 a1 = pack2(a.y, a.y);
            fma2(acc[0][0], a0, b0); fma2(acc[0][1], a0, b1);
            fma2(acc[1][0], a1, b0); fma2(acc[1][1], a1, b1);
        }
        __syncthreads();
    }

    const float* bb = bias + (long)m*3*D_ + 2*D_ + h*HD_ + col0 + tx*4;
    #pragma unroll
    for (int r = 0; r < 2; r++) {
        int row = ty*2 + r;
        float2 v0 = unpack2(acc[r][0]);
        float2 v1 = unpack2(acc[r][1]);
        float4 v = make_float4(v0.x + bb[0], v0.y + bb[1], v1.x + bb[2], v1.y + bb[3]);
        *(float4*)&g_o[((long)m*B_ + row)*D_ + h*HD_ + col0 + tx*4] = v;
    }
}

// ---------------- plastic layer kernels ----------------
__global__ void gates_k(const float* __restrict__ alpha)
{
    int idx = blockIdx.x*256 + threadIdx.x;
    if (idx >= U_*B_*d_) return;
    int j = idx % d_; int b = (idx/d_) % B_; int u = idx/(B_*d_);
    const float* nt = g_nt + ((long)(u*B_ + b))*3*d_ + j*3;
    float pd = nt[0], ps = nt[1], pg = nt[2];
    float inv = 1.f / fmaxf(ps, 1e-6f);
    float dpv = tanhf(g_dp[idx] + pd*inv);
    float srv = 1.f/(1.f + __expf(-(g_sr[idx] + ps)));
    float gbv = 1.f/(1.f + __expf(-(g_gb[idx] + pg*inv)));
    g_dp[idx] = dpv; g_sr[idx] = srv; g_gb[idx] = gbv;
    g_mod[idx] = alpha[(long)u*d_ + j] * dpv * srv;
}

// warp-per-row softmax: grid (U_*B_/4, 2), 128 threads
__global__ __launch_bounds__(128) void rsm_k()
{
    int w = threadIdx.x >> 5, lane = threadIdx.x & 31;
    int row = blockIdx.x*4 + w;
    int which = blockIdx.y;
    const float* src = (which ? g_pr : g_pa) + (long)row*d_;
    float* dst = g_asm + (long)which*U_*B_*d_ + (long)row*d_;
    float v[12];
    float mx = -1e30f;
    #pragma unroll
    for (int i = 0; i < 12; i++) { v[i] = src[lane + i*32]; mx = fmaxf(mx, v[i]); }
    mx = wmax(mx);
    float sum = 0.f;
    #pragma unroll
    for (int i = 0; i < 12; i++) { v[i] = __expf(v[i] - mx); sum += v[i]; }
    sum = wsum(sum);
    float inv = 1.f / sum;
    #pragma unroll
    for (int i = 0; i < 12; i++) dst[lane + i*32] = v[i]*inv;
}

// warp-per-row W update (incl. in-warp sd): grid (d_/4, U_), 128 threads
__global__ __launch_bounds__(128) void wupd_k(const float* __restrict__ decay, int which)
{
    int w = threadIdx.x >> 5, lane = threadIdx.x & 31;
    int i = blockIdx.x*4 + w, u = blockIdx.y;
    float* Wp = (which ? g_Wr : g_W) + ((long)u*d_ + i)*d_;
    const float* Cp = g_C + ((long)(which*U_ + u)*d_ + i)*d_;
    float gv = g_gb[((long)u*B_ + lane)*d_ + i];
    gv = wsum(gv);
    float sd = decay[(long)u*d_ + i] * (1.f/(1.f + __expf(-gv*(1.f/B_))));
    float om = 1.f - sd;
    float wv[12];
    float mx = -1e30f;
    #pragma unroll
    for (int k = 0; k < 12; k++) { wv[k] = Wp[lane + k*32]; mx = fmaxf(mx, wv[k]); }
    mx = wmax(mx);
    float ev[12];
    float sum = 0.f;
    #pragma unroll
    for (int k = 0; k < 12; k++) { ev[k] = __expf(wv[k] - mx); sum += ev[k]; }
    sum = wsum(sum);
    float inv = 1.f / sum;
    #pragma unroll
    for (int k = 0; k < 12; k++)
        Wp[lane + k*32] = wv[k]*om + ev[k]*inv*Cp[lane + k*32];
}

// ---------------- LayerNorm (warp-per-row): grid rows/4, 128 threads ---------
__global__ __launch_bounds__(128) void ln_k(const float* __restrict__ in,
                     float* __restrict__ out1, long o1Group,
                     float* __restrict__ out2,
                     const float* __restrict__ gam, const float* __restrict__ bet,
                     long gGroup, int N)
{
    int w = threadIdx.x >> 5, lane = threadIdx.x & 31;
    int row = blockIdx.x*4 + w;
    int grp = row / B_, rb = row % B_;
    const float* x = in + (long)row*N;
    int nper = N / 32;   // 12 or 24
    float vals[24];
    float s = 0.f;
    for (int t = 0; t < nper; t++) { vals[t] = x[lane + t*32]; s += vals[t]; }
    s = wsum(s);
    float mu = s / N;
    float sq = 0.f;
    for (int t = 0; t < nper; t++) { float dv = vals[t] - mu; sq += dv*dv; }
    sq = wsum(sq);
    float rstd = rsqrtf(sq / N + 1e-5f);
    float* o1 = out1 + (long)grp*o1Group + (long)rb*N;
    const float* gp = gam + (long)grp*gGroup;
    const float* bp = bet + (long)grp*gGroup;
    for (int t = 0; t < nper; t++) {
        int j = lane + t*32;
        float y = (vals[t] - mu)*rstd*gp[j] + bp[j];
        o1[j] = y;
        if (out2) out2[(long)row*N + j] = y;
    }
}

__global__ void clear_k()
{
    long idx = (long)blockIdx.x*256 + threadIdx.x;
    if (idx < (long)U_*B_*d_) {
        g_pa[idx] = 0.f; g_pr[idx] = 0.f; g_dp[idx] = 0.f; g_sr[idx] = 0.f; g_gb[idx] = 0.f;
    }
}

// ---------------- host launcher ----------------
extern "C" void kernel_launch(void* const* d_in, const int* in_sizes, int n_in,
                              void* d_out, int out_size)
{
    const float* x          = (const float*)d_in[0];
    const float* mem0       = (const float*)d_in[1];
    const float* attn_in_w  = (const float*)d_in[2];
    const float* attn_in_b  = (const float*)d_in[3];
    const float* attn_out_w = (const float*)d_in[4];
    const float* attn_out_b = (const float*)d_in[5];
    const float* heb_w      = (const float*)d_in[6];
    const float* heb_rw     = (const float*)d_in[7];
    const float* alpha      = (const float*)d_in[8];
    const float* decay      = (const float*)d_in[9];
    const float* ln_act_g   = (const float*)d_in[10];
    const float* ln_act_b   = (const float*)d_in[11];
    const float* ln_rec_g   = (const float*)d_in[12];
    const float* ln_rec_b   = (const float*)d_in[13];
    const float* pred_w1    = (const float*)d_in[14];
    const float* pred_b1    = (const float*)d_in[15];
    const float* pred_w2    = (const float*)d_in[16];
    const float* pred_b2    = (const float*)d_in[17];
    const float* out_w      = (const float*)d_in[18];
    const float* out_b      = (const float*)d_in[19];
    const float* ln_out_g   = (const float*)d_in[20];
    const float* ln_out_b   = (const float*)d_in[21];

    float *pmem, *pqall, *pqk, *po, *ph, *ppa, *ppr, *pt1, *pnt, *ptmp,
          *poutpre, *pW, *pWr, *pasm, *pmod, *pC;
    cudaGetSymbolAddress((void**)&pmem,    g_mem);
    cudaGetSymbolAddress((void**)&pqall,   g_qall);
    cudaGetSymbolAddress((void**)&pqk,     g_qk);
    cudaGetSymbolAddress((void**)&po,      g_o);
    cudaGetSymbolAddress((void**)&ph,      g_h);
    cudaGetSymbolAddress((void**)&ppa,     g_pa);
    cudaGetSymbolAddress((void**)&ppr,     g_pr);
    cudaGetSymbolAddress((void**)&pt1,     g_t1);
    cudaGetSymbolAddress((void**)&pnt,     g_nt);
    cudaGetSymbolAddress((void**)&ptmp,    g_tmp);
    cudaGetSymbolAddress((void**)&poutpre, g_outpre);
    cudaGetSymbolAddress((void**)&pW,      g_W);
    cudaGetSymbolAddress((void**)&pWr,     g_Wr);
    cudaGetSymbolAddress((void**)&pasm,    g_asm);
    cudaGetSymbolAddress((void**)&pmod,    g_mod);
    cudaGetSymbolAddress((void**)&pC,      g_C);

    static cudaStream_t s1 = nullptr, s2 = nullptr;
    static cudaEvent_t evActs = nullptr, evHeb = nullptr, evGates = nullptr,
                       evW = nullptr, evRsm = nullptr;
    if (!s1) {
        cudaStreamCreateWithFlags(&s1, cudaStreamNonBlocking);
        cudaStreamCreateWithFlags(&s2, cudaStreamNonBlocking);
        cudaEventCreateWithFlags(&evActs,  cudaEventDisableTiming);
        cudaEventCreateWithFlags(&evHeb,   cudaEventDisableTiming);
        cudaEventCreateWithFlags(&evGates, cudaEventDisableTiming);
        cudaEventCreateWithFlags(&evW,     cudaEventDisableTiming);
        cudaEventCreateWithFlags(&evRsm,   cudaEventDisableTiming);
    }
    cudaStream_t s0 = 0;

    const float qscale = 1.f / sqrtf((float)HD_);

    // init state (s0)
    cudaMemcpyAsync(pW,  heb_w,  sizeof(float)*(long)U_*d_*d_, cudaMemcpyDeviceToDevice, s0);
    cudaMemcpyAsync(pWr, heb_rw, sizeof(float)*(long)U_*d_*d_, cudaMemcpyDeviceToDevice, s0);
    cudaMemcpyAsync(pmem, mem0,  sizeof(float)*M_*B_*D_,       cudaMemcpyDeviceToDevice, s0);
    clear_k<<<(U_*B_*d_ + 255)/256, 256, 0, s0>>>();

    // q for all timesteps, then qk = qh @ Wk (per head)
    gemm2_k<0,false,true><<<dim3(12, 8, M_), 128, 0, s0>>>(x, 0, D_,
        attn_in_w, (long)3*D_*D_, 0, 0, attn_in_b, (long)3*D_,
        pqall, (long)T_*B_*D_, D_, D_, qscale);
    gemm2_k<2,false,false><<<dim3(12, 8, M_*H_), 128, 0, s0>>>(pqall, (long)T_*B_*D_, D_,
        attn_in_w + (long)D_*D_, (long)3*D_*D_, 0, (long)HD_*D_,
        nullptr, 0,
        pqk, (long)T_*B_*D_, D_, HD_, 1.f);
    // prime the fork event: heb chain at t=0 starts after init completes
    cudaEventRecord(evActs, s0);

    for (int t = 0; t < T_; t++) {
        // ---- Hebbian front on s1 (needs only prev-step pa/pr/dp/sr/gb) ----
        cudaStreamWaitEvent(s1, evActs, 0);
        gemm3_k<0,0,false><<<dim3(6, 1, U_), 512, 0, s1>>>(ppa, (long)B_*d_, d_,
            pred_w1, (long)d_*d_, pred_b1, (long)d_, nullptr, 0,
            pt1, (long)B_*d_, d_, d_, 1.f, 1);
        gemm3_k<0,0,false><<<dim3(18, 1, U_), 512, 0, s1>>>(pt1, (long)B_*d_, d_,
            pred_w2, (long)d_*3*d_, pred_b2, (long)3*d_, nullptr, 0,
            pnt, (long)B_*3*d_, 3*d_, d_, 1.f, 0);
        gates_k<<<(U_*B_*d_ + 255)/256, 256, 0, s1>>>(alpha);
        cudaEventRecord(evGates, s1);

        // ---- rsm on s2 (independent of t1/nt/gates) ----
        cudaStreamWaitEvent(s2, evActs, 0);
        rsm_k<<<dim3(U_*B_/4, 2), 128, 0, s2>>>();
        cudaEventRecord(evRsm, s2);

        // s2: W-half (outer which=0 + wupd W) — joins at acts
        cudaStreamWaitEvent(s2, evGates, 0);
        gemm2_k<0,true,false><<<dim3(6, 12, U_), 128, 0, s2>>>(pasm, (long)B_*d_, d_,
            pmod, (long)B_*d_, 0, 0, nullptr, 0,
            pC, (long)d_*d_, d_, B_, 1.f/B_);
        wupd_k<<<dim3(d_/4, U_), 128, 0, s2>>>(decay, 0);
        cudaEventRecord(evW, s2);

        // s1: Wr-half (critical path to rec/pr)
        cudaStreamWaitEvent(s1, evRsm, 0);
        gemm2_k<0,true,false><<<dim3(6, 12, U_), 128, 0, s1>>>(pasm + (long)U_*B_*d_, (long)B_*d_, d_,
            pmod, (long)B_*d_, 0, 0, nullptr, 0,
            pC + (long)U_*d_*d_, (long)d_*d_, d_, B_, 1.f/B_);
        wupd_k<<<dim3(d_/4, U_), 128, 0, s1>>>(decay, 1);
        gemm3_k<0,0,false><<<dim3(6, 1, U_), 512, 0, s1>>>(ppa, (long)B_*d_, d_,
            pWr, (long)d_*d_, nullptr, 0, nullptr, 0,
            ptmp, (long)B_*d_, d_, d_, 1.f, 0);
        ln_k<<<U_*B_/4, 128, 0, s1>>>(ptmp, ppr, (long)B_*d_, nullptr,
            ln_rec_g, ln_rec_b, (long)d_, d_);
        cudaEventRecord(evHeb, s1);

        // ---- attention chain on s0 ----
        wmem_k<<<dim3(B_, M_), 256, 0, s0>>>(t);
        attnv_k<<<dim3(3, 1, M_*H_), 128, 0, s0>>>(attn_in_w, attn_in_b);
        gemm3_k<0,1,true><<<dim3(12, 1, M_), 512, 0, s0>>>(po, (long)B_*D_, D_,
            attn_out_w, (long)D_*D_, attn_out_b, (long)D_, nullptr, 0,
            ph, 0, D_, D_, 1.f, 0);

        cudaStreamWaitEvent(s0, evHeb, 0);
        cudaStreamWaitEvent(s0, evW, 0);

        for (int l = 0; l < L_; l++) {
            gemm3_k<0,0,false><<<dim3(6, 1, P_), 512, 0, s0>>>(ph, (long)B_*d_, d_,
                pW + (long)l*d_*d_, (long)L_*d_*d_, nullptr, 0,
                ppr + (long)l*B_*d_, (long)L_*B_*d_,
                ptmp, (long)B_*d_, d_, d_, 1.f, 1);
            ln_k<<<P_*B_/4, 128, 0, s0>>>(ptmp, ppa + (long)l*B_*d_, (long)L_*B_*d_, ph,
                ln_act_g + (long)l*d_, ln_act_b + (long)l*d_, (long)L_*d_, d_);
        }
        // heb state for step t+1 is final here (pa written; pr/W/Wr already done)
        cudaEventRecord(evActs, s0);

        gemm3_k<1,0,true><<<dim3(12, 1, M_), 512, 0, s0>>>(ph, 0, 0,
            out_w, (long)D_*D_, out_b, (long)D_, nullptr, 0,
            poutpre, (long)B_*D_, D_, D_, 1.f, 0);
        ln_k<<<M_*B_/4, 128, 0, s0>>>(poutpre, pmem, (long)B_*D_, nullptr,
            ln_out_g, ln_out_b, (long)D_, D_);
    }

    cudaMemcpyAsync(d_out, pmem, sizeof(float)*M_*B_*D_, cudaMemcpyDeviceToDevice, s0);
}